// round 9
// baseline (speedup 1.0000x reference)
#include <cuda_runtime.h>
#include <cuda_fp16.h>
#include <math.h>

#define NMAX 100000
#define EMAX 1310720
#define DD 64

// -------- persistent scratch (device globals; no allocation allowed) --------
__device__ __align__(16) __half g_Ph[NMAX * 32];     // x @ Wp1[:64]
__device__ __align__(16) __half g_Qh[NMAX * 32];     // x @ Wn1[:64]
__device__ __align__(16) __half g_RSh[NMAX * 64];    // [x@Wp1[64:]+bp1 | x@Wn1[64:]+bn1]
__device__ __align__(16) __half g_xpnh[NMAX * 64];   // [xp | xn]
__device__ __align__(16) __half g_mP2h[NMAX * 64];   // [A|C] = pos-means of [xp|xn]
__device__ __align__(16) __half g_mN2h[NMAX * 64];   // [B|D] = neg-means of [xn|xp]
__device__ __align__(16) int2   g_es[EMAX];          // {src, lid = 2*dst+neg}
__device__ __align__(16) int    g_cnt[2 * NMAX];
__device__ __align__(16) int    g_offs[2 * NMAX + 1];
__device__ __align__(16) int    g_cur[2 * NMAX];
__device__ __align__(16) int    g_csr[EMAX];
__device__ __align__(16) int    g_bsum[256];
__device__ __align__(16) int    g_bpre[256];

// ------------------------------ tiny helpers --------------------------------
__device__ __forceinline__ unsigned packh2(float a, float b) {
    __half2 h = __floats2half2_rn(a, b);
    return *(unsigned*)&h;
}
__device__ __forceinline__ void h8tof(uint4 v, float* o) {
    const __half2* h = (const __half2*)&v;
#pragma unroll
    for (int j = 0; j < 4; j++) {
        float2 f = __half22float2(h[j]);
        o[2 * j] = f.x;
        o[2 * j + 1] = f.y;
    }
}

// ---------------- mma.m16n8k16 f16 -> f32, analytic fragments ---------------
__device__ __forceinline__ void mma16816(float* c, const unsigned* a, const unsigned* b) {
    asm volatile(
        "mma.sync.aligned.m16n8k16.row.col.f32.f16.f16.f32 "
        "{%0,%1,%2,%3}, {%4,%5,%6,%7}, {%8,%9}, {%0,%1,%2,%3};"
        : "+f"(c[0]), "+f"(c[1]), "+f"(c[2]), "+f"(c[3])
        : "r"(a[0]), "r"(a[1]), "r"(a[2]), "r"(a[3]), "r"(b[0]), "r"(b[1]));
}
__device__ __forceinline__ void lda(unsigned* a, const __half* base, int stride,
                                    int k0, int lane) {
    int gr = lane >> 2, gc = lane & 3;
    const __half* p = base + gr * stride + k0 + 2 * gc;
    a[0] = *(const unsigned*)p;
    a[1] = *(const unsigned*)(p + 8 * stride);
    a[2] = *(const unsigned*)(p + 8);
    a[3] = *(const unsigned*)(p + 8 * stride + 8);
}
__device__ __forceinline__ void ldb(unsigned* b, const __half* WT, int stride,
                                    int n0, int k0, int lane) {
    int gn = lane >> 2, gc = lane & 3;
    const __half* p = WT + (n0 + gn) * stride + k0 + 2 * gc;
    b[0] = *(const unsigned*)p;
    b[1] = *(const unsigned*)(p + 8);
}

// ------------------------------- CSR build ----------------------------------
__global__ void k_zcnt(int nlists) {
    int i = blockIdx.x * blockDim.x + threadIdx.x;
    int stride = gridDim.x * blockDim.x;
    for (int j = i; j < nlists; j += stride) g_cnt[j] = 0;
}

__global__ void k_pack(const int* __restrict__ ei, int E) {
    int i = blockIdx.x * blockDim.x + threadIdx.x;
    int stride = gridDim.x * blockDim.x;
    for (int e = i; e < E; e += stride) {
        long eb = 3L * e;
        int s  = __ldg(ei + eb);
        int d  = __ldg(ei + eb + 1);
        int sg = __ldg(ei + eb + 2);
        int lid = 2 * d + ((sg > 0) ? 0 : 1);
        g_es[e] = make_int2(s, lid);
        atomicAdd(&g_cnt[lid], 1);
    }
}

// block b scans 1024 counts (256 thr x 4); exclusive offsets + block total
__global__ void k_scanA(int nlists) {
    __shared__ int ws[8];
    int b = blockIdx.x, tid = threadIdx.x;
    int base = b * 1024 + tid * 4;
    int v[4];
#pragma unroll
    for (int j = 0; j < 4; j++) {
        int i = base + j;
        v[j] = (i < nlists) ? g_cnt[i] : 0;
    }
    int s = v[0] + v[1] + v[2] + v[3];
    int lane = tid & 31, w = tid >> 5;
    int ps = s;
#pragma unroll
    for (int o = 1; o < 32; o <<= 1) {
        int t = __shfl_up_sync(0xffffffffu, ps, o);
        if (lane >= o) ps += t;
    }
    if (lane == 31) ws[w] = ps;
    __syncthreads();
    if (tid < 8) {
        int q = ws[tid];
#pragma unroll
        for (int o = 1; o < 8; o <<= 1) {
            int u = __shfl_up_sync(0xffu, q, o);
            if (tid >= o) q += u;
        }
        ws[tid] = q;
    }
    __syncthreads();
    int wpre = (w > 0) ? ws[w - 1] : 0;
    int run = wpre + ps - s;   // exclusive for this thread's first element
#pragma unroll
    for (int j = 0; j < 4; j++) {
        int i = base + j;
        if (i < nlists) g_offs[i] = run;
        run += v[j];
    }
    if (tid == 255) g_bsum[b] = wpre + ps;
}

// single block: exclusive scan of block sums; writes total offs[nlists]
__global__ void k_scanB(int nb, int nlists) {
    __shared__ int ws[8];
    int tid = threadIdx.x;
    int s = (tid < nb) ? g_bsum[tid] : 0;
    int lane = tid & 31, w = tid >> 5;
    int ps = s;
#pragma unroll
    for (int o = 1; o < 32; o <<= 1) {
        int t = __shfl_up_sync(0xffffffffu, ps, o);
        if (lane >= o) ps += t;
    }
    if (lane == 31) ws[w] = ps;
    __syncthreads();
    if (tid < 8) {
        int q = ws[tid];
#pragma unroll
        for (int o = 1; o < 8; o <<= 1) {
            int u = __shfl_up_sync(0xffu, q, o);
            if (tid >= o) q += u;
        }
        ws[tid] = q;
    }
    __syncthreads();
    int wpre = (w > 0) ? ws[w - 1] : 0;
    if (tid < nb) g_bpre[tid] = wpre + ps - s;
    if (tid == 255) g_offs[nlists] = wpre + ps;
}

__global__ void k_scanC(int nlists) {
    int b = blockIdx.x, tid = threadIdx.x;
    int add = g_bpre[b];
    int base = b * 1024 + tid * 4;
#pragma unroll
    for (int j = 0; j < 4; j++) {
        int i = base + j;
        if (i < nlists) {
            int o = g_offs[i] + add;
            g_offs[i] = o;
            g_cur[i] = o;
        }
    }
}

__global__ void k_scatter(int E) {
    int i = blockIdx.x * blockDim.x + threadIdx.x;
    int stride = gridDim.x * blockDim.x;
    for (int e = i; e < E; e += stride) {
        int2 es = g_es[e];
        int pos = atomicAdd(&g_cur[es.y], 1);
        g_csr[pos] = es.x;
    }
}

// ----------- projection GEMM (tensor cores): [N x 64] @ [64 x 128] ----------
__global__ void __launch_bounds__(256)
k_projTC(const float* __restrict__ x,
         const float* __restrict__ Wp1, const float* __restrict__ bp1,
         const float* __restrict__ Wn1, const float* __restrict__ bn1,
         int n_nodes, int n_tiles) {
    __shared__ __align__(16) __half WT[128 * 72];
    __shared__ float b1s[64];
    int tid = threadIdx.x;
    for (int i = tid; i < 64 * 128; i += 256) {
        int k = i >> 7, col = i & 127;
        float w;
        if (col < 32)       w = Wp1[k * 32 + col];
        else if (col < 64)  w = Wn1[k * 32 + (col - 32)];
        else if (col < 96)  w = Wp1[(64 + k) * 32 + (col - 64)];
        else                w = Wn1[(64 + k) * 32 + (col - 96)];
        WT[col * 72 + k] = __float2half(w);
    }
    if (tid < 32) { b1s[tid] = bp1[tid]; b1s[32 + tid] = bn1[tid]; }
    __syncthreads();

    int wid = tid >> 5, lane = tid & 31;
    int tile = blockIdx.x * 8 + wid;
    if (tile >= n_tiles) return;
    int base = tile * 16;
    int gr = lane >> 2, gc = lane & 3;
    int r0 = base + gr, r1 = base + gr + 8;
    bool v0 = r0 < n_nodes, v1 = r1 < n_nodes;
    size_t rr0 = v0 ? (size_t)r0 : 0, rr1 = v1 ? (size_t)r1 : 0;

    float c[16][4];
#pragma unroll
    for (int t = 0; t < 16; t++)
        c[t][0] = c[t][1] = c[t][2] = c[t][3] = 0.f;

    for (int kc = 0; kc < 4; kc++) {
        unsigned a[4];
        const float* p0 = x + rr0 * 64 + 16 * kc + 2 * gc;
        const float* p1 = x + rr1 * 64 + 16 * kc + 2 * gc;
        float2 f0 = *(const float2*)p0;
        float2 f1 = *(const float2*)p1;
        float2 f2 = *(const float2*)(p0 + 8);
        float2 f3 = *(const float2*)(p1 + 8);
        a[0] = packh2(f0.x, f0.y);
        a[1] = packh2(f1.x, f1.y);
        a[2] = packh2(f2.x, f2.y);
        a[3] = packh2(f3.x, f3.y);
#pragma unroll
        for (int t = 0; t < 16; t++) {
            unsigned b[2];
            ldb(b, WT, 72, 8 * t, 16 * kc, lane);
            mma16816(c[t], a, b);
        }
    }
#pragma unroll
    for (int t = 0; t < 16; t++) {
        int colw = 8 * t + 2 * gc;
        if (colw < 64) {
            __half* dstb = (colw < 32) ? g_Ph : g_Qh;
            int cw = colw & 31;
            if (v0) *(unsigned*)(dstb + rr0 * 32 + cw) = packh2(c[t][0], c[t][1]);
            if (v1) *(unsigned*)(dstb + rr1 * 32 + cw) = packh2(c[t][2], c[t][3]);
        } else {
            float bb0 = b1s[colw - 64], bb1 = b1s[colw - 63];
            if (v0) *(unsigned*)(g_RSh + rr0 * 64 + (colw - 64)) =
                packh2(c[t][0] + bb0, c[t][1] + bb1);
            if (v1) *(unsigned*)(g_RSh + rr1 * 64 + (colw - 64)) =
                packh2(c[t][2] + bb0, c[t][3] + bb1);
        }
    }
}

// ------------- layer-1 aggregation by gather + fused tanh (agg1) ------------
// warp per list (lid = 2*node + neg). 32 lanes = 8 edges x 4 chunks.
// xpn[n][neg*32 + j] = tanh(RS[n][neg*32 + j] + mean)
__global__ void __launch_bounds__(256)
k_agg1(int nlists) {
    int tid = threadIdx.x, lane = tid & 31;
    int wl = blockIdx.x * 8 + (tid >> 5);
    if (wl >= nlists) return;
    int n = wl >> 1, neg = wl & 1;
    int off = g_offs[wl], end = g_offs[wl + 1];
    int deg = end - off;
    const uint4* payload = (const uint4*)(neg ? g_Qh : g_Ph);
    int esub = lane >> 2, chunk = lane & 3;
    float acc[8];
#pragma unroll
    for (int j = 0; j < 8; j++) acc[j] = 0.f;
    for (int it = off + esub; it < end; it += 8) {
        int src = __ldg(g_csr + it);
        uint4 v = payload[(size_t)src * 4 + chunk];
        float f[8];
        h8tof(v, f);
#pragma unroll
        for (int j = 0; j < 8; j++) acc[j] += f[j];
    }
#pragma unroll
    for (int j = 0; j < 8; j++) {
        acc[j] += __shfl_down_sync(0xffffffffu, acc[j], 16);
        acc[j] += __shfl_down_sync(0xffffffffu, acc[j], 8);
        acc[j] += __shfl_down_sync(0xffffffffu, acc[j], 4);
    }
    if (lane < 4) {
        float inv = 1.0f / fmaxf((float)deg, 1.0f);
        uint4 rs = ((const uint4*)g_RSh)[(size_t)n * 8 + neg * 4 + lane];
        float rf[8];
        h8tof(rs, rf);
        uint4 o;
        unsigned* ou = (unsigned*)&o;
#pragma unroll
        for (int j = 0; j < 4; j++)
            ou[j] = packh2(tanhf(rf[2 * j] + acc[2 * j] * inv),
                           tanhf(rf[2 * j + 1] + acc[2 * j + 1] * inv));
        ((uint4*)g_xpnh)[(size_t)n * 8 + neg * 4 + lane] = o;
    }
}

// ------------------- layer-2 aggregation by gather (agg2) -------------------
// warp per list. 32 lanes = 4 edges x 8 chunks. Writes MEANS.
// pos: g_mP2h[n] = [mean xp | mean xn] ; neg: g_mN2h[n] = [mean xn | mean xp]
__global__ void __launch_bounds__(256)
k_agg2(int nlists) {
    int tid = threadIdx.x, lane = tid & 31;
    int wl = blockIdx.x * 8 + (tid >> 5);
    if (wl >= nlists) return;
    int n = wl >> 1, neg = wl & 1;
    int off = g_offs[wl], end = g_offs[wl + 1];
    int deg = end - off;
    int esub = lane >> 3, chunk = lane & 7;
    float acc[8];
#pragma unroll
    for (int j = 0; j < 8; j++) acc[j] = 0.f;
    for (int it = off + esub; it < end; it += 4) {
        int src = __ldg(g_csr + it);
        uint4 v = ((const uint4*)g_xpnh)[(size_t)src * 8 + chunk];
        float f[8];
        h8tof(v, f);
#pragma unroll
        for (int j = 0; j < 8; j++) acc[j] += f[j];
    }
#pragma unroll
    for (int j = 0; j < 8; j++) {
        acc[j] += __shfl_down_sync(0xffffffffu, acc[j], 16);
        acc[j] += __shfl_down_sync(0xffffffffu, acc[j], 8);
    }
    if (lane < 8) {
        float inv = 1.0f / fmaxf((float)deg, 1.0f);
        uint4 o;
        unsigned* ou = (unsigned*)&o;
#pragma unroll
        for (int j = 0; j < 4; j++)
            ou[j] = packh2(acc[2 * j] * inv, acc[2 * j + 1] * inv);
        if (!neg) {
            ((uint4*)g_mP2h)[(size_t)n * 8 + lane] = o;
        } else {
            int cs = (lane + 4) & 7;   // half-swap: [B|D]
            ((uint4*)g_mN2h)[(size_t)n * 8 + cs] = o;
        }
    }
}

// ------------- node layer 2 + MLP head: tensor-core warp tiles --------------
__global__ void __launch_bounds__(256)
k_node2TC(const float* __restrict__ Wp2, const float* __restrict__ bp2,
          const float* __restrict__ Wn2, const float* __restrict__ bn2,
          const float* __restrict__ Ww,  const float* __restrict__ bw,
          const float* __restrict__ Wm1, const float* __restrict__ bm1,
          const float* __restrict__ g1,  const float* __restrict__ be1,
          const float* __restrict__ rm1, const float* __restrict__ rv1,
          const float* __restrict__ Wm2, const float* __restrict__ bm2,
          const float* __restrict__ g2,  const float* __restrict__ be2,
          const float* __restrict__ rm2, const float* __restrict__ rv2,
          const float* __restrict__ Wm3, const float* __restrict__ bm3,
          float* __restrict__ outz, float* __restrict__ outp,
          int n_nodes, int n_tiles) {
    extern __shared__ __align__(16) __half smh[];
    __half* WpT = smh;                    // 32 x 104
    __half* WnT = smh + 3328;             // 32 x 104
    __half* WwT = smh + 6656;             // 64 x 72
    __half* W1T = smh + 11264;            // 64 x 72
    __half* W2T = smh + 15872;            // 64 x 72
    float* fb = (float*)(smh + 56320);
    float* bp2s = fb;         // 32
    float* bn2s = fb + 32;    // 32
    float* bws  = fb + 64;    // 64
    float* sc1  = fb + 128;   // 64
    float* of1  = fb + 192;   // 64
    float* sc2  = fb + 256;   // 64
    float* of2  = fb + 320;   // 64
    float* w3s  = fb + 384;   // 64
    // fb[448] = b3

    int tid = threadIdx.x;
    for (int i = tid; i < 96 * 32; i += 256) {
        int k = i >> 5, nn = i & 31;
        WpT[nn * 104 + k] = __float2half(Wp2[i]);
        WnT[nn * 104 + k] = __float2half(Wn2[i]);
    }
    for (int i = tid; i < 64 * 64; i += 256) {
        int k = i >> 6, nn = i & 63;
        WwT[nn * 72 + k] = __float2half(Ww[i]);
        W1T[nn * 72 + k] = __float2half(Wm1[i]);
        W2T[nn * 72 + k] = __float2half(Wm2[i]);
    }
    if (tid < 32) { bp2s[tid] = bp2[tid]; bn2s[tid] = bn2[tid]; }
    if (tid < 64) {
        bws[tid] = bw[tid];
        float s1 = g1[tid] * rsqrtf(rv1[tid] + 1e-5f);
        sc1[tid] = s1;
        of1[tid] = (bm1[tid] - rm1[tid]) * s1 + be1[tid];
        float s2 = g2[tid] * rsqrtf(rv2[tid] + 1e-5f);
        sc2[tid] = s2;
        of2[tid] = (bm2[tid] - rm2[tid]) * s2 + be2[tid];
        w3s[tid] = Wm3[tid];
    }
    if (tid == 0) fb[448] = bm3[0];
    __syncthreads();

    int wid = tid >> 5, lane = tid & 31;
    __half* Ahp = smh + 20480 + wid * 1664;  // 16 x 104
    __half* Ahn = smh + 33792 + wid * 1664;  // 16 x 104
    __half* zs  = smh + 47104 + wid * 1152;  // 16 x 72

    int tile = blockIdx.x * 8 + wid;
    if (tile >= n_tiles) return;
    int base = tile * 16;
    int gr = lane >> 2, gc = lane & 3;

    // ---- stage inputs (means already divided): Ahp=[A|B|xp], Ahn=[C|D|xn] ----
    {
        int row = lane >> 1, part = lane & 1;
        int n = base + row;
        if (n >= n_nodes) n = n_nodes - 1;
        const uint4* sp = (const uint4*)g_mP2h + (size_t)n * 8;   // [A|C]
        const uint4* sn = (const uint4*)g_mN2h + (size_t)n * 8;   // [B|D]
        const uint4* sx = (const uint4*)g_xpnh + (size_t)n * 8;
        uint4* rp = (uint4*)(Ahp + row * 104);
        uint4* rn = (uint4*)(Ahn + row * 104);
        if (part == 0) {
#pragma unroll
            for (int j = 0; j < 4; j++) {
                rp[j] = sp[j];       // A
                rn[j] = sp[4 + j];   // C
            }
            rp[4] = sn[0]; rp[5] = sn[1];  // B lo
            rn[4] = sn[4]; rn[5] = sn[5];  // D lo
        } else {
            rp[6] = sn[2]; rp[7] = sn[3];  // B hi
            rn[6] = sn[6]; rn[7] = sn[7];  // D hi
#pragma unroll
            for (int j = 0; j < 4; j++) {
                rp[8 + j] = sx[j];        // xp
                rn[8 + j] = sx[4 + j];    // xn
            }
        }
    }
    __syncwarp();

    // ---- loop1: hp (t 0..3), hn (t 4..7), K = 96 ----
    float c1[8][4];
#pragma unroll
    for (int t = 0; t < 8; t++)
        c1[t][0] = c1[t][1] = c1[t][2] = c1[t][3] = 0.f;
    for (int kc = 0; kc < 6; kc++) {
        unsigned a[4], b[2];
        lda(a, Ahp, 104, 16 * kc, lane);
#pragma unroll
        for (int t = 0; t < 4; t++) {
            ldb(b, WpT, 104, 8 * t, 16 * kc, lane);
            mma16816(c1[t], a, b);
        }
        lda(a, Ahn, 104, 16 * kc, lane);
#pragma unroll
        for (int t = 0; t < 4; t++) {
            ldb(b, WnT, 104, 8 * t, 16 * kc, lane);
            mma16816(c1[4 + t], a, b);
        }
    }
    __syncwarp();
#pragma unroll
    for (int t = 0; t < 8; t++) {
        int c32 = 8 * (t & 3) + 2 * gc;
        const float* barr = (t < 4) ? bp2s : bn2s;
        float b0 = barr[c32], b1 = barr[c32 + 1];
        int cz = (t < 4) ? c32 : 32 + c32;
        *(unsigned*)(zs + gr * 72 + cz) =
            packh2(tanhf(c1[t][0] + b0), tanhf(c1[t][1] + b1));
        *(unsigned*)(zs + (gr + 8) * 72 + cz) =
            packh2(tanhf(c1[t][2] + b0), tanhf(c1[t][3] + b1));
    }
    __syncwarp();

    int nr0 = base + gr, nr1 = base + gr + 8;
    bool v0 = nr0 < n_nodes, v1 = nr1 < n_nodes;

    // ---- loop2: z = tanh(z2 @ Ww + bw) ----
    float c2[8][4];
#pragma unroll
    for (int t = 0; t < 8; t++)
        c2[t][0] = c2[t][1] = c2[t][2] = c2[t][3] = 0.f;
    for (int kc = 0; kc < 4; kc++) {
        unsigned a[4], b[2];
        lda(a, zs, 72, 16 * kc, lane);
#pragma unroll
        for (int t = 0; t < 8; t++) {
            ldb(b, WwT, 72, 8 * t, 16 * kc, lane);
            mma16816(c2[t], a, b);
        }
    }
    __syncwarp();
#pragma unroll
    for (int t = 0; t < 8; t++) {
        int col = 8 * t + 2 * gc;
        float z0 = tanhf(c2[t][0] + bws[col]);
        float z1 = tanhf(c2[t][1] + bws[col + 1]);
        float z2v = tanhf(c2[t][2] + bws[col]);
        float z3 = tanhf(c2[t][3] + bws[col + 1]);
        if (v0) *(float2*)(outz + (size_t)nr0 * 64 + col) = make_float2(z0, z1);
        if (v1) *(float2*)(outz + (size_t)nr1 * 64 + col) = make_float2(z2v, z3);
        *(unsigned*)(zs + gr * 72 + col) = packh2(z0, z1);
        *(unsigned*)(zs + (gr + 8) * 72 + col) = packh2(z2v, z3);
    }
    __syncwarp();

    // ---- loop3: h = relu(bn1(z @ Wm1)) ----
#pragma unroll
    for (int t = 0; t < 8; t++)
        c2[t][0] = c2[t][1] = c2[t][2] = c2[t][3] = 0.f;
    for (int kc = 0; kc < 4; kc++) {
        unsigned a[4], b[2];
        lda(a, zs, 72, 16 * kc, lane);
#pragma unroll
        for (int t = 0; t < 8; t++) {
            ldb(b, W1T, 72, 8 * t, 16 * kc, lane);
            mma16816(c2[t], a, b);
        }
    }
    __syncwarp();
#pragma unroll
    for (int t = 0; t < 8; t++) {
        int col = 8 * t + 2 * gc;
        float h0 = fmaxf(c2[t][0] * sc1[col] + of1[col], 0.f);
        float h1 = fmaxf(c2[t][1] * sc1[col + 1] + of1[col + 1], 0.f);
        float h2 = fmaxf(c2[t][2] * sc1[col] + of1[col], 0.f);
        float h3 = fmaxf(c2[t][3] * sc1[col + 1] + of1[col + 1], 0.f);
        *(unsigned*)(zs + gr * 72 + col) = packh2(h0, h1);
        *(unsigned*)(zs + (gr + 8) * 72 + col) = packh2(h2, h3);
    }
    __syncwarp();

    // ---- loop4: r = relu(bn2(h @ Wm2)); prob = sigmoid(r.w3 + b3) ----
#pragma unroll
    for (int t = 0; t < 8; t++)
        c2[t][0] = c2[t][1] = c2[t][2] = c2[t][3] = 0.f;
    for (int kc = 0; kc < 4; kc++) {
        unsigned a[4], b[2];
        lda(a, zs, 72, 16 * kc, lane);
#pragma unroll
        for (int t = 0; t < 8; t++) {
            ldb(b, W2T, 72, 8 * t, 16 * kc, lane);
            mma16816(c2[t], a, b);
        }
    }
    float p0 = 0.f, p1 = 0.f;
#pragma unroll
    for (int t = 0; t < 8; t++) {
        int col = 8 * t + 2 * gc;
        float r0 = fmaxf(c2[t][0] * sc2[col] + of2[col], 0.f);
        float r1 = fmaxf(c2[t][1] * sc2[col + 1] + of2[col + 1], 0.f);
        float r2 = fmaxf(c2[t][2] * sc2[col] + of2[col], 0.f);
        float r3 = fmaxf(c2[t][3] * sc2[col + 1] + of2[col + 1], 0.f);
        p0 += r0 * w3s[col] + r1 * w3s[col + 1];
        p1 += r2 * w3s[col] + r3 * w3s[col + 1];
    }
    p0 += __shfl_xor_sync(0xffffffffu, p0, 1);
    p0 += __shfl_xor_sync(0xffffffffu, p0, 2);
    p1 += __shfl_xor_sync(0xffffffffu, p1, 1);
    p1 += __shfl_xor_sync(0xffffffffu, p1, 2);
    if ((lane & 3) == 0) {
        float b3 = fb[448];
        if (v0) outp[nr0] = 1.0f / (1.0f + expf(-(p0 + b3)));
        if (v1) outp[nr1] = 1.0f / (1.0f + expf(-(p1 + b3)));
    }
}

// -------------------------------- launcher ----------------------------------
extern "C" void kernel_launch(void* const* d_in, const int* in_sizes, int n_in,
                              void* d_out, int out_size) {
    const float* x   = (const float*)d_in[0];
    const int*   ei  = (const int*)d_in[1];
    const float* Wp1 = (const float*)d_in[2];
    const float* bp1 = (const float*)d_in[3];
    const float* Wn1 = (const float*)d_in[4];
    const float* bn1 = (const float*)d_in[5];
    const float* Wp2 = (const float*)d_in[6];
    const float* bp2 = (const float*)d_in[7];
    const float* Wn2 = (const float*)d_in[8];
    const float* bn2 = (const float*)d_in[9];
    const float* Ww  = (const float*)d_in[10];
    const float* bw  = (const float*)d_in[11];
    const float* Wm1 = (const float*)d_in[12];
    const float* bm1 = (const float*)d_in[13];
    const float* g1  = (const float*)d_in[14];
    const float* be1 = (const float*)d_in[15];
    const float* rm1 = (const float*)d_in[16];
    const float* rv1 = (const float*)d_in[17];
    const float* Wm2 = (const float*)d_in[18];
    const float* bm2 = (const float*)d_in[19];
    const float* g2  = (const float*)d_in[20];
    const float* be2 = (const float*)d_in[21];
    const float* rm2 = (const float*)d_in[22];
    const float* rv2 = (const float*)d_in[23];
    const float* Wm3 = (const float*)d_in[24];
    const float* bm3 = (const float*)d_in[25];

    int Nn = in_sizes[0] / DD;
    int E  = in_sizes[1] / 3;

    float* out  = (float*)d_out;
    float* outz = out;
    float* outp = out + (size_t)Nn * DD;

    int n_tiles = (Nn + 15) / 16;
    int n_blks  = (n_tiles + 7) / 8;
    int nlists  = 2 * Nn;
    int nb      = (nlists + 1023) / 1024;

    const int NODE2_SMEM = 56320 * 2 + 452 * 4;  // 114448 B
    cudaFuncSetAttribute(k_node2TC, cudaFuncAttributeMaxDynamicSharedMemorySize,
                         NODE2_SMEM);

    // CSR build
    k_zcnt<<<256, 256>>>(nlists);
    k_pack<<<1280, 256>>>(ei, E);
    k_scanA<<<nb, 256>>>(nlists);
    k_scanB<<<1, 256>>>(nb, nlists);
    k_scanC<<<nb, 256>>>(nlists);
    k_scatter<<<1280, 256>>>(E);

    // node/edge pipeline
    k_projTC<<<n_blks, 256>>>(x, Wp1, bp1, Wn1, bn1, Nn, n_tiles);
    k_agg1<<<(nlists + 7) / 8, 256>>>(nlists);
    k_agg2<<<(nlists + 7) / 8, 256>>>(nlists);
    k_node2TC<<<n_blks, 256, NODE2_SMEM>>>(
        Wp2, bp2, Wn2, bn2, Ww, bw,
        Wm1, bm1, g1, be1, rm1, rv1,
        Wm2, bm2, g2, be2, rm2, rv2,
        Wm3, bm3, outz, outp, Nn, n_tiles);
}

// round 10
// speedup vs baseline: 1.3667x; 1.3667x over previous
#include <cuda_runtime.h>
#include <cuda_fp16.h>
#include <math.h>

#define NMAX 100000
#define EMAX 1310720
#define DD 64

// -------- persistent scratch (device globals; no allocation allowed) --------
__device__ __align__(16) __half g_Ph[NMAX * 32];     // x @ Wp1[:64]
__device__ __align__(16) __half g_Qh[NMAX * 32];     // x @ Wn1[:64]
__device__ __align__(16) __half g_RSh[NMAX * 64];    // [x@Wp1[64:]+bp1 | x@Wn1[64:]+bn1]
__device__ __align__(16) __half g_accPh[NMAX * 32];
__device__ __align__(16) __half g_accNh[NMAX * 32];
__device__ __align__(16) __half g_xpnh[NMAX * 64];   // [xp | xn]
__device__ __align__(16) __half g_accP2h[NMAX * 64]; // pos: [sum xp | sum xn] = [A|C]
__device__ __align__(16) __half g_accN2h[NMAX * 64]; // neg: [sum xn | sum xp] = [B|D]
__device__ __align__(16) float  g_cntp[NMAX];
__device__ __align__(16) float  g_cntn[NMAX];
__device__ __align__(16) int2   g_es[EMAX];          // {src, dst or ~dst(neg)}

// ------------------------------ tiny helpers --------------------------------
__device__ __forceinline__ void red_v4h(__half* p, uint4 v) {
    asm volatile("red.global.add.noftz.v4.f16x2 [%0], {%1,%2,%3,%4};"
                 :: "l"(p), "r"(v.x), "r"(v.y), "r"(v.z), "r"(v.w)
                 : "memory");
}
__device__ __forceinline__ unsigned packh2(float a, float b) {
    __half2 h = __floats2half2_rn(a, b);
    return *(unsigned*)&h;
}
__device__ __forceinline__ void h8tof(uint4 v, float* o) {
    const __half2* h = (const __half2*)&v;
#pragma unroll
    for (int j = 0; j < 4; j++) {
        float2 f = __half22float2(h[j]);
        o[2 * j] = f.x;
        o[2 * j + 1] = f.y;
    }
}

// ---------------- mma.m16n8k16 f16 -> f32, analytic fragments ---------------
__device__ __forceinline__ void mma16816(float* c, const unsigned* a, const unsigned* b) {
    asm volatile(
        "mma.sync.aligned.m16n8k16.row.col.f32.f16.f16.f32 "
        "{%0,%1,%2,%3}, {%4,%5,%6,%7}, {%8,%9}, {%0,%1,%2,%3};"
        : "+f"(c[0]), "+f"(c[1]), "+f"(c[2]), "+f"(c[3])
        : "r"(a[0]), "r"(a[1]), "r"(a[2]), "r"(a[3]), "r"(b[0]), "r"(b[1]));
}
// A row-major [16 x K] in smem, stride in halves (even), k0 multiple of 16
__device__ __forceinline__ void lda(unsigned* a, const __half* base, int stride,
                                    int k0, int lane) {
    int gr = lane >> 2, gc = lane & 3;
    const __half* p = base + gr * stride + k0 + 2 * gc;
    a[0] = *(const unsigned*)p;
    a[1] = *(const unsigned*)(p + 8 * stride);
    a[2] = *(const unsigned*)(p + 8);
    a[3] = *(const unsigned*)(p + 8 * stride + 8);
}
// B as WT[n][k] row-major (= B col-major), stride in halves
__device__ __forceinline__ void ldb(unsigned* b, const __half* WT, int stride,
                                    int n0, int k0, int lane) {
    int gn = lane >> 2, gc = lane & 3;
    const __half* p = WT + (n0 + gn) * stride + k0 + 2 * gc;
    b[0] = *(const unsigned*)p;
    b[1] = *(const unsigned*)(p + 8);
}
// loop1 A-operand element pair straight from gmem.
// logical col ka in [0,96): [0,32)=accP2*ivp, [32,64)=accN2*ivn, [64,96)=xpn.
// off = 0 for the "p" variant (A|B|xp), 32 for the "n" variant (C|D|xn).
__device__ __forceinline__ unsigned ldA96(int n, int ka, int off,
                                          __half2 ivp, __half2 ivn) {
    __half2 v;
    if (ka < 32) {
        v = *(const __half2*)(g_accP2h + (size_t)n * 64 + off + ka);
        v = __hmul2(v, ivp);
    } else if (ka < 64) {
        v = *(const __half2*)(g_accN2h + (size_t)n * 64 + off + (ka - 32));
        v = __hmul2(v, ivn);
    } else {
        v = *(const __half2*)(g_xpnh + (size_t)n * 64 + off + (ka - 64));
    }
    return *(unsigned*)&v;
}

// ------------------- init: pack edges + zero accumulators -------------------
__global__ void k_init(const int* __restrict__ ei, int E, int n) {
    int i = blockIdx.x * blockDim.x + threadIdx.x;
    int stride = gridDim.x * blockDim.x;
    for (int e = i; e < E; e += stride) {
        long eb = 3L * e;
        int s  = __ldg(ei + eb);
        int d  = __ldg(ei + eb + 1);
        int sg = __ldg(ei + eb + 2);
        g_es[e] = make_int2(s, (sg > 0) ? d : ~d);
    }
    uint4 z4 = make_uint4(0u, 0u, 0u, 0u);
    int nh = n * 4;
    for (int j = i; j < nh; j += stride) {
        ((uint4*)g_accPh)[j] = z4;
        ((uint4*)g_accNh)[j] = z4;
    }
    int nd = n * 8;
    for (int j = i; j < nd; j += stride) {
        ((uint4*)g_accP2h)[j] = z4;
        ((uint4*)g_accN2h)[j] = z4;
    }
    int nc = n / 4;
    for (int j = i; j < nc; j += stride) {
        ((uint4*)g_cntp)[j] = z4;
        ((uint4*)g_cntn)[j] = z4;
    }
}

// ----------- projection GEMM (tensor cores): [N x 64] @ [64 x 128] ----------
__global__ void __launch_bounds__(256)
k_projTC(const float* __restrict__ x,
         const float* __restrict__ Wp1, const float* __restrict__ bp1,
         const float* __restrict__ Wn1, const float* __restrict__ bn1,
         int n_nodes, int n_tiles) {
    __shared__ __align__(16) __half WT[128 * 72];
    __shared__ float b1s[64];
    int tid = threadIdx.x;
    for (int i = tid; i < 64 * 128; i += 256) {
        int k = i >> 7, col = i & 127;
        float w;
        if (col < 32)       w = Wp1[k * 32 + col];
        else if (col < 64)  w = Wn1[k * 32 + (col - 32)];
        else if (col < 96)  w = Wp1[(64 + k) * 32 + (col - 64)];
        else                w = Wn1[(64 + k) * 32 + (col - 96)];
        WT[col * 72 + k] = __float2half(w);
    }
    if (tid < 32) { b1s[tid] = bp1[tid]; b1s[32 + tid] = bn1[tid]; }
    __syncthreads();

    int wid = tid >> 5, lane = tid & 31;
    int tile = blockIdx.x * 8 + wid;
    if (tile >= n_tiles) return;
    int base = tile * 16;
    int gr = lane >> 2, gc = lane & 3;
    int r0 = base + gr, r1 = base + gr + 8;
    bool v0 = r0 < n_nodes, v1 = r1 < n_nodes;
    size_t rr0 = v0 ? (size_t)r0 : 0, rr1 = v1 ? (size_t)r1 : 0;

    float c[16][4];
#pragma unroll
    for (int t = 0; t < 16; t++)
        c[t][0] = c[t][1] = c[t][2] = c[t][3] = 0.f;

    for (int kc = 0; kc < 4; kc++) {
        unsigned a[4];
        const float* p0 = x + rr0 * 64 + 16 * kc + 2 * gc;
        const float* p1 = x + rr1 * 64 + 16 * kc + 2 * gc;
        float2 f0 = *(const float2*)p0;
        float2 f1 = *(const float2*)p1;
        float2 f2 = *(const float2*)(p0 + 8);
        float2 f3 = *(const float2*)(p1 + 8);
        a[0] = packh2(f0.x, f0.y);
        a[1] = packh2(f1.x, f1.y);
        a[2] = packh2(f2.x, f2.y);
        a[3] = packh2(f3.x, f3.y);
#pragma unroll
        for (int t = 0; t < 16; t++) {
            unsigned b[2];
            ldb(b, WT, 72, 8 * t, 16 * kc, lane);
            mma16816(c[t], a, b);
        }
    }
#pragma unroll
    for (int t = 0; t < 16; t++) {
        int colw = 8 * t + 2 * gc;
        if (colw < 64) {
            __half* dstb = (colw < 32) ? g_Ph : g_Qh;
            int cw = colw & 31;
            if (v0) *(unsigned*)(dstb + rr0 * 32 + cw) = packh2(c[t][0], c[t][1]);
            if (v1) *(unsigned*)(dstb + rr1 * 32 + cw) = packh2(c[t][2], c[t][3]);
        } else {
            float bb0 = b1s[colw - 64], bb1 = b1s[colw - 63];
            if (v0) *(unsigned*)(g_RSh + rr0 * 64 + (colw - 64)) =
                packh2(c[t][0] + bb0, c[t][1] + bb1);
            if (v1) *(unsigned*)(g_RSh + rr1 * 64 + (colw - 64)) =
                packh2(c[t][2] + bb0, c[t][3] + bb1);
        }
    }
}

// --------------------------- layer-1 aggregation ----------------------------
// 2 edges per thread; 4 chunk-threads per edge pair.
__global__ void k_edge1(int npairs, int E) {
    long idx = (long)blockIdx.x * blockDim.x + threadIdx.x;
    int p = (int)(idx >> 2);
    if (p >= npairs) return;
    int c = (int)(idx & 3);
    int4 es = __ldg((const int4*)g_es + p);
    bool has1 = (2 * p + 1 < E);

    int s0 = es.x, d0 = es.y;
    bool pos0 = (d0 >= 0);
    if (!pos0) d0 = ~d0;
    int s1 = es.z, d1 = es.w;
    bool pos1 = (d1 >= 0);
    if (!pos1) d1 = ~d1;

    uint4 v0 = *((const uint4*)(pos0 ? g_Ph : g_Qh) + (size_t)s0 * 4 + c);
    uint4 v1;
    if (has1) v1 = *((const uint4*)(pos1 ? g_Ph : g_Qh) + (size_t)s1 * 4 + c);

    red_v4h((pos0 ? g_accPh : g_accNh) + (size_t)d0 * 32 + c * 8, v0);
    if (c == 0) atomicAdd(pos0 ? (g_cntp + d0) : (g_cntn + d0), 1.0f);
    if (has1) {
        red_v4h((pos1 ? g_accPh : g_accNh) + (size_t)d1 * 32 + c * 8, v1);
        if (c == 0) atomicAdd(pos1 ? (g_cntp + d1) : (g_cntn + d1), 1.0f);
    }
}

// --------------------- node layer 1: elementwise tanh -----------------------
__global__ void k_node1e(long total) {
    long idx = (long)blockIdx.x * blockDim.x + threadIdx.x;
    if (idx >= total) return;
    int n = (int)(idx >> 3);
    int c = (int)(idx & 7);
    uint4 rs = ((const uint4*)g_RSh)[idx];
    uint4 acc;
    float inv;
    if (c < 4) {
        acc = ((const uint4*)g_accPh)[(size_t)n * 4 + c];
        inv = 1.0f / fmaxf(g_cntp[n], 1.0f);
    } else {
        acc = ((const uint4*)g_accNh)[(size_t)n * 4 + (c - 4)];
        inv = 1.0f / fmaxf(g_cntn[n], 1.0f);
    }
    float rf[8], af[8];
    h8tof(rs, rf);
    h8tof(acc, af);
    uint4 o;
    unsigned* ou = (unsigned*)&o;
#pragma unroll
    for (int j = 0; j < 4; j++)
        ou[j] = packh2(tanhf(rf[2 * j] + af[2 * j] * inv),
                       tanhf(rf[2 * j + 1] + af[2 * j + 1] * inv));
    ((uint4*)g_xpnh)[idx] = o;
}

// --------------------------- layer-2 aggregation ----------------------------
// 2 edges per thread; 8 chunk-threads per edge pair.
__global__ void k_edge2(int npairs, int E) {
    long idx = (long)blockIdx.x * blockDim.x + threadIdx.x;
    int p = (int)(idx >> 3);
    if (p >= npairs) return;
    int c = (int)(idx & 7);
    int4 es = __ldg((const int4*)g_es + p);
    bool has1 = (2 * p + 1 < E);

    int s0 = es.x, d0 = es.y;
    int s1 = es.z, d1 = es.w;

    uint4 v0 = *((const uint4*)g_xpnh + (size_t)s0 * 8 + c);
    uint4 v1;
    if (has1) v1 = *((const uint4*)g_xpnh + (size_t)s1 * 8 + c);

    if (d0 >= 0) {
        red_v4h(g_accP2h + (size_t)d0 * 64 + c * 8, v0);
    } else {
        red_v4h(g_accN2h + (size_t)(~d0) * 64 + (((c + 4) & 7)) * 8, v0);
    }
    if (has1) {
        if (d1 >= 0) {
            red_v4h(g_accP2h + (size_t)d1 * 64 + c * 8, v1);
        } else {
            red_v4h(g_accN2h + (size_t)(~d1) * 64 + (((c + 4) & 7)) * 8, v1);
        }
    }
}

// ------------- node layer 2 + MLP head: tensor-core warp tiles --------------
// loop1 A-operands come straight from gmem (no smem staging) -> smem 61KB,
// >=2 blocks/SM.
__global__ void __launch_bounds__(256, 2)
k_node2TC(const float* __restrict__ Wp2, const float* __restrict__ bp2,
          const float* __restrict__ Wn2, const float* __restrict__ bn2,
          const float* __restrict__ Ww,  const float* __restrict__ bw,
          const float* __restrict__ Wm1, const float* __restrict__ bm1,
          const float* __restrict__ g1,  const float* __restrict__ be1,
          const float* __restrict__ rm1, const float* __restrict__ rv1,
          const float* __restrict__ Wm2, const float* __restrict__ bm2,
          const float* __restrict__ g2,  const float* __restrict__ be2,
          const float* __restrict__ rm2, const float* __restrict__ rv2,
          const float* __restrict__ Wm3, const float* __restrict__ bm3,
          float* __restrict__ outz, float* __restrict__ outp,
          int n_nodes, int n_tiles) {
    extern __shared__ __align__(16) __half smh[];
    __half* WpT = smh;                    // 32 x 104
    __half* WnT = smh + 3328;             // 32 x 104
    __half* WwT = smh + 6656;             // 64 x 72
    __half* W1T = smh + 11264;            // 64 x 72
    __half* W2T = smh + 15872;            // 64 x 72
    // per-warp z-tile: 16 x 72 halves each
    float* fb = (float*)(smh + 29696);
    float* bp2s = fb;         // 32
    float* bn2s = fb + 32;    // 32
    float* bws  = fb + 64;    // 64
    float* sc1  = fb + 128;   // 64
    float* of1  = fb + 192;   // 64
    float* sc2  = fb + 256;   // 64
    float* of2  = fb + 320;   // 64
    float* w3s  = fb + 384;   // 64
    // fb[448] = b3

    int tid = threadIdx.x;
    for (int i = tid; i < 96 * 32; i += 256) {
        int k = i >> 5, nn = i & 31;
        WpT[nn * 104 + k] = __float2half(Wp2[i]);
        WnT[nn * 104 + k] = __float2half(Wn2[i]);
    }
    for (int i = tid; i < 64 * 64; i += 256) {
        int k = i >> 6, nn = i & 63;
        WwT[nn * 72 + k] = __float2half(Ww[i]);
        W1T[nn * 72 + k] = __float2half(Wm1[i]);
        W2T[nn * 72 + k] = __float2half(Wm2[i]);
    }
    if (tid < 32) { bp2s[tid] = bp2[tid]; bn2s[tid] = bn2[tid]; }
    if (tid < 64) {
        bws[tid] = bw[tid];
        float s1 = g1[tid] * rsqrtf(rv1[tid] + 1e-5f);
        sc1[tid] = s1;
        of1[tid] = (bm1[tid] - rm1[tid]) * s1 + be1[tid];
        float s2 = g2[tid] * rsqrtf(rv2[tid] + 1e-5f);
        sc2[tid] = s2;
        of2[tid] = (bm2[tid] - rm2[tid]) * s2 + be2[tid];
        w3s[tid] = Wm3[tid];
    }
    if (tid == 0) fb[448] = bm3[0];
    __syncthreads();

    int wid = tid >> 5, lane = tid & 31;
    __half* zs = smh + 20480 + wid * 1152;  // 16 x 72

    int tile = blockIdx.x * 8 + wid;
    if (tile >= n_tiles) return;
    int base = tile * 16;
    int gr = lane >> 2, gc = lane & 3;

    int nr0 = base + gr, nr1 = base + gr + 8;
    bool v0 = nr0 < n_nodes, v1 = nr1 < n_nodes;
    int n0 = v0 ? nr0 : (n_nodes - 1);
    int n1 = v1 ? nr1 : (n_nodes - 1);

    __half2 ivp0 = __float2half2_rn(1.0f / fmaxf(g_cntp[n0], 1.0f));
    __half2 ivn0 = __float2half2_rn(1.0f / fmaxf(g_cntn[n0], 1.0f));
    __half2 ivp1 = __float2half2_rn(1.0f / fmaxf(g_cntp[n1], 1.0f));
    __half2 ivn1 = __float2half2_rn(1.0f / fmaxf(g_cntn[n1], 1.0f));

    // ---- loop1: hp (t 0..3 via WpT), hn (t 4..7 via WnT), K = 96, A from gmem
    float c1[8][4];
#pragma unroll
    for (int t = 0; t < 8; t++)
        c1[t][0] = c1[t][1] = c1[t][2] = c1[t][3] = 0.f;
#pragma unroll
    for (int kc = 0; kc < 6; kc++) {
        int ka = 16 * kc + 2 * gc;
        unsigned a[4], b[2];
        // p-variant: [A | B | xp]
        a[0] = ldA96(n0, ka, 0, ivp0, ivn0);
        a[1] = ldA96(n1, ka, 0, ivp1, ivn1);
        a[2] = ldA96(n0, ka + 8, 0, ivp0, ivn0);
        a[3] = ldA96(n1, ka + 8, 0, ivp1, ivn1);
#pragma unroll
        for (int t = 0; t < 4; t++) {
            ldb(b, WpT, 104, 8 * t, 16 * kc, lane);
            mma16816(c1[t], a, b);
        }
        // n-variant: [C | D | xn]
        a[0] = ldA96(n0, ka, 32, ivp0, ivn0);
        a[1] = ldA96(n1, ka, 32, ivp1, ivn1);
        a[2] = ldA96(n0, ka + 8, 32, ivp0, ivn0);
        a[3] = ldA96(n1, ka + 8, 32, ivp1, ivn1);
#pragma unroll
        for (int t = 0; t < 4; t++) {
            ldb(b, WnT, 104, 8 * t, 16 * kc, lane);
            mma16816(c1[4 + t], a, b);
        }
    }
#pragma unroll
    for (int t = 0; t < 8; t++) {
        int c32 = 8 * (t & 3) + 2 * gc;
        const float* barr = (t < 4) ? bp2s : bn2s;
        float b0 = barr[c32], b1 = barr[c32 + 1];
        int cz = (t < 4) ? c32 : 32 + c32;
        *(unsigned*)(zs + gr * 72 + cz) =
            packh2(tanhf(c1[t][0] + b0), tanhf(c1[t][1] + b1));
        *(unsigned*)(zs + (gr + 8) * 72 + cz) =
            packh2(tanhf(c1[t][2] + b0), tanhf(c1[t][3] + b1));
    }
    __syncwarp();

    // ---- loop2: z = tanh(z2 @ Ww + bw) ----
    float c2[8][4];
#pragma unroll
    for (int t = 0; t < 8; t++)
        c2[t][0] = c2[t][1] = c2[t][2] = c2[t][3] = 0.f;
    for (int kc = 0; kc < 4; kc++) {
        unsigned a[4], b[2];
        lda(a, zs, 72, 16 * kc, lane);
#pragma unroll
        for (int t = 0; t < 8; t++) {
            ldb(b, WwT, 72, 8 * t, 16 * kc, lane);
            mma16816(c2[t], a, b);
        }
    }
    __syncwarp();
#pragma unroll
    for (int t = 0; t < 8; t++) {
        int col = 8 * t + 2 * gc;
        float z0 = tanhf(c2[t][0] + bws[col]);
        float z1 = tanhf(c2[t][1] + bws[col + 1]);
        float z2v = tanhf(c2[t][2] + bws[col]);
        float z3 = tanhf(c2[t][3] + bws[col + 1]);
        if (v0) *(float2*)(outz + (size_t)nr0 * 64 + col) = make_float2(z0, z1);
        if (v1) *(float2*)(outz + (size_t)nr1 * 64 + col) = make_float2(z2v, z3);
        *(unsigned*)(zs + gr * 72 + col) = packh2(z0, z1);
        *(unsigned*)(zs + (gr + 8) * 72 + col) = packh2(z2v, z3);
    }
    __syncwarp();

    // ---- loop3: h = relu(bn1(z @ Wm1)) ----
#pragma unroll
    for (int t = 0; t < 8; t++)
        c2[t][0] = c2[t][1] = c2[t][2] = c2[t][3] = 0.f;
    for (int kc = 0; kc < 4; kc++) {
        unsigned a[4], b[2];
        lda(a, zs, 72, 16 * kc, lane);
#pragma unroll
        for (int t = 0; t < 8; t++) {
            ldb(b, W1T, 72, 8 * t, 16 * kc, lane);
            mma16816(c2[t], a, b);
        }
    }
    __syncwarp();
#pragma unroll
    for (int t = 0; t < 8; t++) {
        int col = 8 * t + 2 * gc;
        float h0 = fmaxf(c2[t][0] * sc1[col] + of1[col], 0.f);
        float h1 = fmaxf(c2[t][1] * sc1[col + 1] + of1[col + 1], 0.f);
        float h2 = fmaxf(c2[t][2] * sc1[col] + of1[col], 0.f);
        float h3 = fmaxf(c2[t][3] * sc1[col + 1] + of1[col + 1], 0.f);
        *(unsigned*)(zs + gr * 72 + col) = packh2(h0, h1);
        *(unsigned*)(zs + (gr + 8) * 72 + col) = packh2(h2, h3);
    }
    __syncwarp();

    // ---- loop4: r = relu(bn2(h @ Wm2)); prob = sigmoid(r.w3 + b3) ----
#pragma unroll
    for (int t = 0; t < 8; t++)
        c2[t][0] = c2[t][1] = c2[t][2] = c2[t][3] = 0.f;
    for (int kc = 0; kc < 4; kc++) {
        unsigned a[4], b[2];
        lda(a, zs, 72, 16 * kc, lane);
#pragma unroll
        for (int t = 0; t < 8; t++) {
            ldb(b, W2T, 72, 8 * t, 16 * kc, lane);
            mma16816(c2[t], a, b);
        }
    }
    float p0 = 0.f, p1 = 0.f;
#pragma unroll
    for (int t = 0; t < 8; t++) {
        int col = 8 * t + 2 * gc;
        float r0 = fmaxf(c2[t][0] * sc2[col] + of2[col], 0.f);
        float r1 = fmaxf(c2[t][1] * sc2[col + 1] + of2[col + 1], 0.f);
        float r2 = fmaxf(c2[t][2] * sc2[col] + of2[col], 0.f);
        float r3 = fmaxf(c2[t][3] * sc2[col + 1] + of2[col + 1], 0.f);
        p0 += r0 * w3s[col] + r1 * w3s[col + 1];
        p1 += r2 * w3s[col] + r3 * w3s[col + 1];
    }
    p0 += __shfl_xor_sync(0xffffffffu, p0, 1);
    p0 += __shfl_xor_sync(0xffffffffu, p0, 2);
    p1 += __shfl_xor_sync(0xffffffffu, p1, 1);
    p1 += __shfl_xor_sync(0xffffffffu, p1, 2);
    if ((lane & 3) == 0) {
        float b3 = fb[448];
        if (v0) outp[nr0] = 1.0f / (1.0f + expf(-(p0 + b3)));
        if (v1) outp[nr1] = 1.0f / (1.0f + expf(-(p1 + b3)));
    }
}

// -------------------------------- launcher ----------------------------------
extern "C" void kernel_launch(void* const* d_in, const int* in_sizes, int n_in,
                              void* d_out, int out_size) {
    const float* x   = (const float*)d_in[0];
    const int*   ei  = (const int*)d_in[1];
    const float* Wp1 = (const float*)d_in[2];
    const float* bp1 = (const float*)d_in[3];
    const float* Wn1 = (const float*)d_in[4];
    const float* bn1 = (const float*)d_in[5];
    const float* Wp2 = (const float*)d_in[6];
    const float* bp2 = (const float*)d_in[7];
    const float* Wn2 = (const float*)d_in[8];
    const float* bn2 = (const float*)d_in[9];
    const float* Ww  = (const float*)d_in[10];
    const float* bw  = (const float*)d_in[11];
    const float* Wm1 = (const float*)d_in[12];
    const float* bm1 = (const float*)d_in[13];
    const float* g1  = (const float*)d_in[14];
    const float* be1 = (const float*)d_in[15];
    const float* rm1 = (const float*)d_in[16];
    const float* rv1 = (const float*)d_in[17];
    const float* Wm2 = (const float*)d_in[18];
    const float* bm2 = (const float*)d_in[19];
    const float* g2  = (const float*)d_in[20];
    const float* be2 = (const float*)d_in[21];
    const float* rm2 = (const float*)d_in[22];
    const float* rv2 = (const float*)d_in[23];
    const float* Wm3 = (const float*)d_in[24];
    const float* bm3 = (const float*)d_in[25];

    int Nn = in_sizes[0] / DD;
    int E  = in_sizes[1] / 3;

    float* out  = (float*)d_out;
    float* outz = out;
    float* outp = out + (size_t)Nn * DD;

    int n_tiles = (Nn + 15) / 16;
    int n_blks  = (n_tiles + 7) / 8;
    int npairs  = (E + 1) / 2;

    const int NODE2_SMEM = 29696 * 2 + 452 * 4;  // 61200 B
    cudaFuncSetAttribute(k_node2TC, cudaFuncAttributeMaxDynamicSharedMemorySize,
                         NODE2_SMEM);

    k_init<<<2048, 256>>>(ei, E, Nn);

    k_projTC<<<n_blks, 256>>>(x, Wp1, bp1, Wn1, bn1, Nn, n_tiles);

    long t1 = (long)npairs * 4;
    k_edge1<<<(int)((t1 + 255) / 256), 256>>>(npairs, E);

    long tn = (long)Nn * 8;
    k_node1e<<<(int)((tn + 255) / 256), 256>>>(tn);

    long t2 = (long)npairs * 8;
    k_edge2<<<(int)((t2 + 255) / 256), 256>>>(npairs, E);

    k_node2TC<<<n_blks, 256, NODE2_SMEM>>>(
        Wp2, bp2, Wn2, bn2, Ww, bw,
        Wm1, bm1, g1, be1, rm1, rv1,
        Wm2, bm2, g2, be2, rm2, rv2,
        Wm3, bm3, outz, outp, Nn, n_tiles);
}

// round 11
// speedup vs baseline: 1.3848x; 1.0132x over previous
#include <cuda_runtime.h>
#include <cuda_fp16.h>
#include <math.h>

#define NMAX 100000
#define EMAX 1310720
#define DD 64

// -------- persistent scratch (device globals; no allocation allowed) --------
__device__ __align__(16) __half g_Ph[NMAX * 32];     // x @ Wp1[:64]
__device__ __align__(16) __half g_Qh[NMAX * 32];     // x @ Wn1[:64]
__device__ __align__(16) __half g_RSh[NMAX * 64];    // [x@Wp1[64:]+bp1 | x@Wn1[64:]+bn1]
__device__ __align__(16) __half g_accPh[NMAX * 32];
__device__ __align__(16) __half g_accNh[NMAX * 32];
__device__ __align__(16) __half g_xpnh[NMAX * 64];   // [xp | xn]
__device__ __align__(16) __half g_accP2h[NMAX * 64]; // pos: [sum xp | sum xn] = [A|C]
__device__ __align__(16) __half g_accN2h[NMAX * 64]; // neg: [sum xn | sum xp] = [B|D]
__device__ __align__(16) float  g_cntp[NMAX];        // zeroed at END of node2TC
__device__ __align__(16) float  g_cntn[NMAX];
__device__ __align__(16) int2   g_es[EMAX];          // {src, dst or ~dst(neg)}

// ------------------------------ tiny helpers --------------------------------
__device__ __forceinline__ void red_v4h(__half* p, uint4 v) {
    asm volatile("red.global.add.noftz.v4.f16x2 [%0], {%1,%2,%3,%4};"
                 :: "l"(p), "r"(v.x), "r"(v.y), "r"(v.z), "r"(v.w)
                 : "memory");
}
__device__ __forceinline__ unsigned packh2(float a, float b) {
    __half2 h = __floats2half2_rn(a, b);
    return *(unsigned*)&h;
}
__device__ __forceinline__ void h8tof(uint4 v, float* o) {
    const __half2* h = (const __half2*)&v;
#pragma unroll
    for (int j = 0; j < 4; j++) {
        float2 f = __half22float2(h[j]);
        o[2 * j] = f.x;
        o[2 * j + 1] = f.y;
    }
}
// fast tanh: 1 - 2/(exp(2x)+1); inf-safe at both ends, rel err ~1e-6
__device__ __forceinline__ float ftanh(float x) {
    float e = __expf(2.0f * x);
    return 1.0f - __fdividef(2.0f, e + 1.0f);
}

// ---------------- mma.m16n8k16 f16 -> f32, analytic fragments ---------------
__device__ __forceinline__ void mma16816(float* c, const unsigned* a, const unsigned* b) {
    asm volatile(
        "mma.sync.aligned.m16n8k16.row.col.f32.f16.f16.f32 "
        "{%0,%1,%2,%3}, {%4,%5,%6,%7}, {%8,%9}, {%0,%1,%2,%3};"
        : "+f"(c[0]), "+f"(c[1]), "+f"(c[2]), "+f"(c[3])
        : "r"(a[0]), "r"(a[1]), "r"(a[2]), "r"(a[3]), "r"(b[0]), "r"(b[1]));
}
// A row-major [16 x K] in smem, stride in halves (even), k0 multiple of 16
__device__ __forceinline__ void lda(unsigned* a, const __half* base, int stride,
                                    int k0, int lane) {
    int gr = lane >> 2, gc = lane & 3;
    const __half* p = base + gr * stride + k0 + 2 * gc;
    a[0] = *(const unsigned*)p;
    a[1] = *(const unsigned*)(p + 8 * stride);
    a[2] = *(const unsigned*)(p + 8);
    a[3] = *(const unsigned*)(p + 8 * stride + 8);
}
// B as WT[n][k] row-major (= B col-major), stride in halves
__device__ __forceinline__ void ldb(unsigned* b, const __half* WT, int stride,
                                    int n0, int k0, int lane) {
    int gn = lane >> 2, gc = lane & 3;
    const __half* p = WT + (n0 + gn) * stride + k0 + 2 * gc;
    b[0] = *(const unsigned*)p;
    b[1] = *(const unsigned*)(p + 8);
}
// loop1 A-operand element pair straight from gmem.
// logical col ka in [0,96): [0,32)=accP2*ivp, [32,64)=accN2*ivn, [64,96)=xpn.
// off = 0 for the "p" variant (A|B|xp), 32 for the "n" variant (C|D|xn).
__device__ __forceinline__ unsigned ldA96(int n, int ka, int off,
                                          __half2 ivp, __half2 ivn) {
    __half2 v;
    if (ka < 32) {
        v = *(const __half2*)(g_accP2h + (size_t)n * 64 + off + ka);
        v = __hmul2(v, ivp);
    } else if (ka < 64) {
        v = *(const __half2*)(g_accN2h + (size_t)n * 64 + off + (ka - 32));
        v = __hmul2(v, ivn);
    } else {
        v = *(const __half2*)(g_xpnh + (size_t)n * 64 + off + (ka - 64));
    }
    return *(unsigned*)&v;
}

// ---------- fused init (pack edges + counts + zero accs) + projection -------
// blocks [0, n_blks_proj): projection GEMM [N x 64] @ [64 x 128]
// blocks [n_blks_proj, gridDim.x): edge pack + count atomics + acc zeroing
// (g_cntp/g_cntn are zero at launch start: module-load zeros on first call,
//  node2TC tail re-zeroes them each launch.)
__global__ void __launch_bounds__(256)
k_initproj(const float* __restrict__ x,
           const float* __restrict__ Wp1, const float* __restrict__ bp1,
           const float* __restrict__ Wn1, const float* __restrict__ bn1,
           const int* __restrict__ ei, int E, int n_nodes, int n_tiles,
           int n_blks_proj) {
    int tid = threadIdx.x;
    if ((int)blockIdx.x >= n_blks_proj) {
        // ---------------- init partition ----------------
        int ib = blockIdx.x - n_blks_proj;
        int nib = gridDim.x - n_blks_proj;
        int i = ib * 256 + tid;
        int stride = nib * 256;
        for (int e = i; e < E; e += stride) {
            long eb = 3L * e;
            int s  = __ldg(ei + eb);
            int d  = __ldg(ei + eb + 1);
            int sg = __ldg(ei + eb + 2);
            bool pos = (sg > 0);
            g_es[e] = make_int2(s, pos ? d : ~d);
            atomicAdd(pos ? (g_cntp + d) : (g_cntn + d), 1.0f);
        }
        uint4 z4 = make_uint4(0u, 0u, 0u, 0u);
        int nh = n_nodes * 4;
        for (int j = i; j < nh; j += stride) {
            ((uint4*)g_accPh)[j] = z4;
            ((uint4*)g_accNh)[j] = z4;
        }
        int nd = n_nodes * 8;
        for (int j = i; j < nd; j += stride) {
            ((uint4*)g_accP2h)[j] = z4;
            ((uint4*)g_accN2h)[j] = z4;
        }
        return;
    }

    // ---------------- projection partition ----------------
    __shared__ __align__(16) __half WT[128 * 72];
    __shared__ float b1s[64];
    for (int i = tid; i < 64 * 128; i += 256) {
        int k = i >> 7, col = i & 127;
        float w;
        if (col < 32)       w = Wp1[k * 32 + col];
        else if (col < 64)  w = Wn1[k * 32 + (col - 32)];
        else if (col < 96)  w = Wp1[(64 + k) * 32 + (col - 64)];
        else                w = Wn1[(64 + k) * 32 + (col - 96)];
        WT[col * 72 + k] = __float2half(w);
    }
    if (tid < 32) { b1s[tid] = bp1[tid]; b1s[32 + tid] = bn1[tid]; }
    __syncthreads();

    int wid = tid >> 5, lane = tid & 31;
    int tile = blockIdx.x * 8 + wid;
    if (tile >= n_tiles) return;
    int base = tile * 16;
    int gr = lane >> 2, gc = lane & 3;
    int r0 = base + gr, r1 = base + gr + 8;
    bool v0 = r0 < n_nodes, v1 = r1 < n_nodes;
    size_t rr0 = v0 ? (size_t)r0 : 0, rr1 = v1 ? (size_t)r1 : 0;

    float c[16][4];
#pragma unroll
    for (int t = 0; t < 16; t++)
        c[t][0] = c[t][1] = c[t][2] = c[t][3] = 0.f;

    for (int kc = 0; kc < 4; kc++) {
        unsigned a[4];
        const float* p0 = x + rr0 * 64 + 16 * kc + 2 * gc;
        const float* p1 = x + rr1 * 64 + 16 * kc + 2 * gc;
        float2 f0 = *(const float2*)p0;
        float2 f1 = *(const float2*)p1;
        float2 f2 = *(const float2*)(p0 + 8);
        float2 f3 = *(const float2*)(p1 + 8);
        a[0] = packh2(f0.x, f0.y);
        a[1] = packh2(f1.x, f1.y);
        a[2] = packh2(f2.x, f2.y);
        a[3] = packh2(f3.x, f3.y);
#pragma unroll
        for (int t = 0; t < 16; t++) {
            unsigned b[2];
            ldb(b, WT, 72, 8 * t, 16 * kc, lane);
            mma16816(c[t], a, b);
        }
    }
#pragma unroll
    for (int t = 0; t < 16; t++) {
        int colw = 8 * t + 2 * gc;
        if (colw < 64) {
            __half* dstb = (colw < 32) ? g_Ph : g_Qh;
            int cw = colw & 31;
            if (v0) *(unsigned*)(dstb + rr0 * 32 + cw) = packh2(c[t][0], c[t][1]);
            if (v1) *(unsigned*)(dstb + rr1 * 32 + cw) = packh2(c[t][2], c[t][3]);
        } else {
            float bb0 = b1s[colw - 64], bb1 = b1s[colw - 63];
            if (v0) *(unsigned*)(g_RSh + rr0 * 64 + (colw - 64)) =
                packh2(c[t][0] + bb0, c[t][1] + bb1);
            if (v1) *(unsigned*)(g_RSh + rr1 * 64 + (colw - 64)) =
                packh2(c[t][2] + bb0, c[t][3] + bb1);
        }
    }
}

// --------------------------- layer-1 aggregation ----------------------------
// 2 edges per thread; 4 chunk-threads per edge pair. (counts done in init)
__global__ void k_edge1(int npairs, int E) {
    long idx = (long)blockIdx.x * blockDim.x + threadIdx.x;
    int p = (int)(idx >> 2);
    if (p >= npairs) return;
    int c = (int)(idx & 3);
    int4 es = __ldg((const int4*)g_es + p);
    bool has1 = (2 * p + 1 < E);

    int s0 = es.x, d0 = es.y;
    bool pos0 = (d0 >= 0);
    if (!pos0) d0 = ~d0;
    int s1 = es.z, d1 = es.w;
    bool pos1 = (d1 >= 0);
    if (!pos1) d1 = ~d1;

    uint4 v0 = *((const uint4*)(pos0 ? g_Ph : g_Qh) + (size_t)s0 * 4 + c);
    uint4 v1;
    if (has1) v1 = *((const uint4*)(pos1 ? g_Ph : g_Qh) + (size_t)s1 * 4 + c);

    red_v4h((pos0 ? g_accPh : g_accNh) + (size_t)d0 * 32 + c * 8, v0);
    if (has1)
        red_v4h((pos1 ? g_accPh : g_accNh) + (size_t)d1 * 32 + c * 8, v1);
}

// --------------------- node layer 1: elementwise tanh -----------------------
__global__ void k_node1e(long total) {
    long idx = (long)blockIdx.x * blockDim.x + threadIdx.x;
    if (idx >= total) return;
    int n = (int)(idx >> 3);
    int c = (int)(idx & 7);
    uint4 rs = ((const uint4*)g_RSh)[idx];
    uint4 acc;
    float inv;
    if (c < 4) {
        acc = ((const uint4*)g_accPh)[(size_t)n * 4 + c];
        inv = 1.0f / fmaxf(g_cntp[n], 1.0f);
    } else {
        acc = ((const uint4*)g_accNh)[(size_t)n * 4 + (c - 4)];
        inv = 1.0f / fmaxf(g_cntn[n], 1.0f);
    }
    float rf[8], af[8];
    h8tof(rs, rf);
    h8tof(acc, af);
    uint4 o;
    unsigned* ou = (unsigned*)&o;
#pragma unroll
    for (int j = 0; j < 4; j++)
        ou[j] = packh2(ftanh(rf[2 * j] + af[2 * j] * inv),
                       ftanh(rf[2 * j + 1] + af[2 * j + 1] * inv));
    ((uint4*)g_xpnh)[idx] = o;
}

// --------------------------- layer-2 aggregation ----------------------------
// 2 edges per thread; 8 chunk-threads per edge pair.
__global__ void k_edge2(int npairs, int E) {
    long idx = (long)blockIdx.x * blockDim.x + threadIdx.x;
    int p = (int)(idx >> 3);
    if (p >= npairs) return;
    int c = (int)(idx & 7);
    int4 es = __ldg((const int4*)g_es + p);
    bool has1 = (2 * p + 1 < E);

    int s0 = es.x, d0 = es.y;
    int s1 = es.z, d1 = es.w;

    uint4 v0 = *((const uint4*)g_xpnh + (size_t)s0 * 8 + c);
    uint4 v1;
    if (has1) v1 = *((const uint4*)g_xpnh + (size_t)s1 * 8 + c);

    if (d0 >= 0) {
        red_v4h(g_accP2h + (size_t)d0 * 64 + c * 8, v0);
    } else {
        red_v4h(g_accN2h + (size_t)(~d0) * 64 + (((c + 4) & 7)) * 8, v0);
    }
    if (has1) {
        if (d1 >= 0) {
            red_v4h(g_accP2h + (size_t)d1 * 64 + c * 8, v1);
        } else {
            red_v4h(g_accN2h + (size_t)(~d1) * 64 + (((c + 4) & 7)) * 8, v1);
        }
    }
}

// ------------- node layer 2 + MLP head: tensor-core warp tiles --------------
// loop1 A-operands straight from gmem; cnt arrays re-zeroed after use.
__global__ void __launch_bounds__(256, 2)
k_node2TC(const float* __restrict__ Wp2, const float* __restrict__ bp2,
          const float* __restrict__ Wn2, const float* __restrict__ bn2,
          const float* __restrict__ Ww,  const float* __restrict__ bw,
          const float* __restrict__ Wm1, const float* __restrict__ bm1,
          const float* __restrict__ g1,  const float* __restrict__ be1,
          const float* __restrict__ rm1, const float* __restrict__ rv1,
          const float* __restrict__ Wm2, const float* __restrict__ bm2,
          const float* __restrict__ g2,  const float* __restrict__ be2,
          const float* __restrict__ rm2, const float* __restrict__ rv2,
          const float* __restrict__ Wm3, const float* __restrict__ bm3,
          float* __restrict__ outz, float* __restrict__ outp,
          int n_nodes, int n_tiles) {
    extern __shared__ __align__(16) __half smh[];
    __half* WpT = smh;                    // 32 x 104
    __half* WnT = smh + 3328;             // 32 x 104
    __half* WwT = smh + 6656;             // 64 x 72
    __half* W1T = smh + 11264;            // 64 x 72
    __half* W2T = smh + 15872;            // 64 x 72
    // per-warp z-tile: 16 x 72 halves each
    float* fb = (float*)(smh + 29696);
    float* bp2s = fb;         // 32
    float* bn2s = fb + 32;    // 32
    float* bws  = fb + 64;    // 64
    float* sc1  = fb + 128;   // 64
    float* of1  = fb + 192;   // 64
    float* sc2  = fb + 256;   // 64
    float* of2  = fb + 320;   // 64
    float* w3s  = fb + 384;   // 64
    // fb[448] = b3

    int tid = threadIdx.x;
    for (int i = tid; i < 96 * 32; i += 256) {
        int k = i >> 5, nn = i & 31;
        WpT[nn * 104 + k] = __float2half(Wp2[i]);
        WnT[nn * 104 + k] = __float2half(Wn2[i]);
    }
    for (int i = tid; i < 64 * 64; i += 256) {
        int k = i >> 6, nn = i & 63;
        WwT[nn * 72 + k] = __float2half(Ww[i]);
        W1T[nn * 72 + k] = __float2half(Wm1[i]);
        W2T[nn * 72 + k] = __float2half(Wm2[i]);
    }
    if (tid < 32) { bp2s[tid] = bp2[tid]; bn2s[tid] = bn2[tid]; }
    if (tid < 64) {
        bws[tid] = bw[tid];
        float s1 = g1[tid] * rsqrtf(rv1[tid] + 1e-5f);
        sc1[tid] = s1;
        of1[tid] = (bm1[tid] - rm1[tid]) * s1 + be1[tid];
        float s2 = g2[tid] * rsqrtf(rv2[tid] + 1e-5f);
        sc2[tid] = s2;
        of2[tid] = (bm2[tid] - rm2[tid]) * s2 + be2[tid];
        w3s[tid] = Wm3[tid];
    }
    if (tid == 0) fb[448] = bm3[0];
    __syncthreads();

    int wid = tid >> 5, lane = tid & 31;
    __half* zs = smh + 20480 + wid * 1152;  // 16 x 72

    int tile = blockIdx.x * 8 + wid;
    if (tile >= n_tiles) return;
    int base = tile * 16;
    int gr = lane >> 2, gc = lane & 3;

    int nr0 = base + gr, nr1 = base + gr + 8;
    bool v0 = nr0 < n_nodes, v1 = nr1 < n_nodes;
    int n0 = v0 ? nr0 : (n_nodes - 1);
    int n1 = v1 ? nr1 : (n_nodes - 1);

    __half2 ivp0 = __float2half2_rn(1.0f / fmaxf(g_cntp[n0], 1.0f));
    __half2 ivn0 = __float2half2_rn(1.0f / fmaxf(g_cntn[n0], 1.0f));
    __half2 ivp1 = __float2half2_rn(1.0f / fmaxf(g_cntp[n1], 1.0f));
    __half2 ivn1 = __float2half2_rn(1.0f / fmaxf(g_cntn[n1], 1.0f));
    __syncwarp();
    // re-zero counts for next launch (each valid node owned by exactly one
    // tile; padding tiles that read a just-zeroed count only produce values
    // that are discarded by the v0/v1 store guards)
    if (lane < 16) {
        int nz = base + lane;
        if (nz < n_nodes) { g_cntp[nz] = 0.f; g_cntn[nz] = 0.f; }
    }

    // ---- loop1: hp (t 0..3 via WpT), hn (t 4..7 via WnT), K = 96, A from gmem
    float c1[8][4];
#pragma unroll
    for (int t = 0; t < 8; t++)
        c1[t][0] = c1[t][1] = c1[t][2] = c1[t][3] = 0.f;
#pragma unroll
    for (int kc = 0; kc < 6; kc++) {
        int ka = 16 * kc + 2 * gc;
        unsigned a[4], b[2];
        // p-variant: [A | B | xp]
        a[0] = ldA96(n0, ka, 0, ivp0, ivn0);
        a[1] = ldA96(n1, ka, 0, ivp1, ivn1);
        a[2] = ldA96(n0, ka + 8, 0, ivp0, ivn0);
        a[3] = ldA96(n1, ka + 8, 0, ivp1, ivn1);
#pragma unroll
        for (int t = 0; t < 4; t++) {
            ldb(b, WpT, 104, 8 * t, 16 * kc, lane);
            mma16816(c1[t], a, b);
        }
        // n-variant: [C | D | xn]
        a[0] = ldA96(n0, ka, 32, ivp0, ivn0);
        a[1] = ldA96(n1, ka, 32, ivp1, ivn1);
        a[2] = ldA96(n0, ka + 8, 32, ivp0, ivn0);
        a[3] = ldA96(n1, ka + 8, 32, ivp1, ivn1);
#pragma unroll
        for (int t = 0; t < 4; t++) {
            ldb(b, WnT, 104, 8 * t, 16 * kc, lane);
            mma16816(c1[4 + t], a, b);
        }
    }
#pragma unroll
    for (int t = 0; t < 8; t++) {
        int c32 = 8 * (t & 3) + 2 * gc;
        const float* barr = (t < 4) ? bp2s : bn2s;
        float b0 = barr[c32], b1 = barr[c32 + 1];
        int cz = (t < 4) ? c32 : 32 + c32;
        *(unsigned*)(zs + gr * 72 + cz) =
            packh2(ftanh(c1[t][0] + b0), ftanh(c1[t][1] + b1));
        *(unsigned*)(zs + (gr + 8) * 72 + cz) =
            packh2(ftanh(c1[t][2] + b0), ftanh(c1[t][3] + b1));
    }
    __syncwarp();

    // ---- loop2: z = tanh(z2 @ Ww + bw) ----
    float c2[8][4];
#pragma unroll
    for (int t = 0; t < 8; t++)
        c2[t][0] = c2[t][1] = c2[t][2] = c2[t][3] = 0.f;
    for (int kc = 0; kc < 4; kc++) {
        unsigned a[4], b[2];
        lda(a, zs, 72, 16 * kc, lane);
#pragma unroll
        for (int t = 0; t < 8; t++) {
            ldb(b, WwT, 72, 8 * t, 16 * kc, lane);
            mma16816(c2[t], a, b);
        }
    }
    __syncwarp();
#pragma unroll
    for (int t = 0; t < 8; t++) {
        int col = 8 * t + 2 * gc;
        float z0 = ftanh(c2[t][0] + bws[col]);
        float z1 = ftanh(c2[t][1] + bws[col + 1]);
        float z2v = ftanh(c2[t][2] + bws[col]);
        float z3 = ftanh(c2[t][3] + bws[col + 1]);
        if (v0) *(float2*)(outz + (size_t)nr0 * 64 + col) = make_float2(z0, z1);
        if (v1) *(float2*)(outz + (size_t)nr1 * 64 + col) = make_float2(z2v, z3);
        *(unsigned*)(zs + gr * 72 + col) = packh2(z0, z1);
        *(unsigned*)(zs + (gr + 8) * 72 + col) = packh2(z2v, z3);
    }
    __syncwarp();

    // ---- loop3: h = relu(bn1(z @ Wm1)) ----
#pragma unroll
    for (int t = 0; t < 8; t++)
        c2[t][0] = c2[t][1] = c2[t][2] = c2[t][3] = 0.f;
    for (int kc = 0; kc < 4; kc++) {
        unsigned a[4], b[2];
        lda(a, zs, 72, 16 * kc, lane);
#pragma unroll
        for (int t = 0; t < 8; t++) {
            ldb(b, W1T, 72, 8 * t, 16 * kc, lane);
            mma16816(c2[t], a, b);
        }
    }
    __syncwarp();
#pragma unroll
    for (int t = 0; t < 8; t++) {
        int col = 8 * t + 2 * gc;
        float h0 = fmaxf(c2[t][0] * sc1[col] + of1[col], 0.f);
        float h1 = fmaxf(c2[t][1] * sc1[col + 1] + of1[col + 1], 0.f);
        float h2 = fmaxf(c2[t][2] * sc1[col] + of1[col], 0.f);
        float h3 = fmaxf(c2[t][3] * sc1[col + 1] + of1[col + 1], 0.f);
        *(unsigned*)(zs + gr * 72 + col) = packh2(h0, h1);
        *(unsigned*)(zs + (gr + 8) * 72 + col) = packh2(h2, h3);
    }
    __syncwarp();

    // ---- loop4: r = relu(bn2(h @ Wm2)); prob = sigmoid(r.w3 + b3) ----
#pragma unroll
    for (int t = 0; t < 8; t++)
        c2[t][0] = c2[t][1] = c2[t][2] = c2[t][3] = 0.f;
    for (int kc = 0; kc < 4; kc++) {
        unsigned a[4], b[2];
        lda(a, zs, 72, 16 * kc, lane);
#pragma unroll
        for (int t = 0; t < 8; t++) {
            ldb(b, W2T, 72, 8 * t, 16 * kc, lane);
            mma16816(c2[t], a, b);
        }
    }
    float p0 = 0.f, p1 = 0.f;
#pragma unroll
    for (int t = 0; t < 8; t++) {
        int col = 8 * t + 2 * gc;
        float r0 = fmaxf(c2[t][0] * sc2[col] + of2[col], 0.f);
        float r1 = fmaxf(c2[t][1] * sc2[col + 1] + of2[col + 1], 0.f);
        float r2 = fmaxf(c2[t][2] * sc2[col] + of2[col], 0.f);
        float r3 = fmaxf(c2[t][3] * sc2[col + 1] + of2[col + 1], 0.f);
        p0 += r0 * w3s[col] + r1 * w3s[col + 1];
        p1 += r2 * w3s[col] + r3 * w3s[col + 1];
    }
    p0 += __shfl_xor_sync(0xffffffffu, p0, 1);
    p0 += __shfl_xor_sync(0xffffffffu, p0, 2);
    p1 += __shfl_xor_sync(0xffffffffu, p1, 1);
    p1 += __shfl_xor_sync(0xffffffffu, p1, 2);
    if ((lane & 3) == 0) {
        float b3 = fb[448];
        if (v0) outp[nr0] = __fdividef(1.0f, 1.0f + __expf(-(p0 + b3)));
        if (v1) outp[nr1] = __fdividef(1.0f, 1.0f + __expf(-(p1 + b3)));
    }
}

// -------------------------------- launcher ----------------------------------
extern "C" void kernel_launch(void* const* d_in, const int* in_sizes, int n_in,
                              void* d_out, int out_size) {
    const float* x   = (const float*)d_in[0];
    const int*   ei  = (const int*)d_in[1];
    const float* Wp1 = (const float*)d_in[2];
    const float* bp1 = (const float*)d_in[3];
    const float* Wn1 = (const float*)d_in[4];
    const float* bn1 = (const float*)d_in[5];
    const float* Wp2 = (const float*)d_in[6];
    const float* bp2 = (const float*)d_in[7];
    const float* Wn2 = (const float*)d_in[8];
    const float* bn2 = (const float*)d_in[9];
    const float* Ww  = (const float*)d_in[10];
    const float* bw  = (const float*)d_in[11];
    const float* Wm1 = (const float*)d_in[12];
    const float* bm1 = (const float*)d_in[13];
    const float* g1  = (const float*)d_in[14];
    const float* be1 = (const float*)d_in[15];
    const float* rm1 = (const float*)d_in[16];
    const float* rv1 = (const float*)d_in[17];
    const float* Wm2 = (const float*)d_in[18];
    const float* bm2 = (const float*)d_in[19];
    const float* g2  = (const float*)d_in[20];
    const float* be2 = (const float*)d_in[21];
    const float* rm2 = (const float*)d_in[22];
    const float* rv2 = (const float*)d_in[23];
    const float* Wm3 = (const float*)d_in[24];
    const float* bm3 = (const float*)d_in[25];

    int Nn = in_sizes[0] / DD;
    int E  = in_sizes[1] / 3;

    float* out  = (float*)d_out;
    float* outz = out;
    float* outp = out + (size_t)Nn * DD;

    int n_tiles = (Nn + 15) / 16;
    int n_blks_proj = (n_tiles + 7) / 8;
    int n_blks_init = 512;
    int npairs  = (E + 1) / 2;

    const int NODE2_SMEM = 29696 * 2 + 452 * 4;  // 61200 B
    cudaFuncSetAttribute(k_node2TC, cudaFuncAttributeMaxDynamicSharedMemorySize,
                         NODE2_SMEM);

    k_initproj<<<n_blks_proj + n_blks_init, 256>>>(
        x, Wp1, bp1, Wn1, bn1, ei, E, Nn, n_tiles, n_blks_proj);

    long t1 = (long)npairs * 4;
    k_edge1<<<(int)((t1 + 255) / 256), 256>>>(npairs, E);

    long tn = (long)Nn * 8;
    k_node1e<<<(int)((tn + 255) / 256), 256>>>(tn);

    long t2 = (long)npairs * 8;
    k_edge2<<<(int)((t2 + 255) / 256), 256>>>(npairs, E);

    k_node2TC<<<n_blks_proj, 256, NODE2_SMEM>>>(
        Wp2, bp2, Wn2, bn2, Ww, bw,
        Wm1, bm1, g1, be1, rm1, rv1,
        Wm2, bm2, g2, be2, rm2, rv2,
        Wm3, bm3, outz, outp, Nn, n_tiles);
}

// round 12
// speedup vs baseline: 1.5767x; 1.1386x over previous
#include <cuda_runtime.h>
#include <cuda_fp16.h>
#include <math.h>

#define NMAX 100000
#define EMAX 1310720
#define DD 64

// -------- persistent scratch (device globals; no allocation allowed) --------
__device__ __align__(16) __half g_Ph[NMAX * 32];     // x @ Wp1[:64]
__device__ __align__(16) __half g_Qh[NMAX * 32];     // x @ Wn1[:64]
__device__ __align__(16) __half g_RSh[NMAX * 64];    // [x@Wp1[64:]+bp1 | x@Wn1[64:]+bn1]
__device__ __align__(16) __half g_accPh[NMAX * 32];
__device__ __align__(16) __half g_accNh[NMAX * 32];
__device__ __align__(16) __half g_xpnh[NMAX * 64];   // [xp | xn]
__device__ __align__(16) __half g_accP2h[NMAX * 64]; // pos: [sum xp | sum xn] = [A|C]
__device__ __align__(16) __half g_accN2h[NMAX * 64]; // neg: [sum xn | sum xp] = [B|D]
__device__ __align__(16) float  g_cntp[NMAX];        // zeroed at END of node2TC
__device__ __align__(16) float  g_cntn[NMAX];
__device__ __align__(16) int2   g_es[EMAX];          // {src, dst or ~dst(neg)}

// ------------------------------ tiny helpers --------------------------------
__device__ __forceinline__ void red_v4h(__half* p, uint4 v) {
    asm volatile("red.global.add.noftz.v4.f16x2 [%0], {%1,%2,%3,%4};"
                 :: "l"(p), "r"(v.x), "r"(v.y), "r"(v.z), "r"(v.w)
                 : "memory");
}
__device__ __forceinline__ unsigned packh2(float a, float b) {
    __half2 h = __floats2half2_rn(a, b);
    return *(unsigned*)&h;
}
__device__ __forceinline__ void h8tof(uint4 v, float* o) {
    const __half2* h = (const __half2*)&v;
#pragma unroll
    for (int j = 0; j < 4; j++) {
        float2 f = __half22float2(h[j]);
        o[2 * j] = f.x;
        o[2 * j + 1] = f.y;
    }
}
// fast tanh: 1 - 2/(exp(2x)+1); inf-safe at both ends, rel err ~1e-6
__device__ __forceinline__ float ftanh(float x) {
    float e = __expf(2.0f * x);
    return 1.0f - __fdividef(2.0f, e + 1.0f);
}

// ---------------- mma.m16n8k16 f16 -> f32, analytic fragments ---------------
__device__ __forceinline__ void mma16816(float* c, const unsigned* a, const unsigned* b) {
    asm volatile(
        "mma.sync.aligned.m16n8k16.row.col.f32.f16.f16.f32 "
        "{%0,%1,%2,%3}, {%4,%5,%6,%7}, {%8,%9}, {%0,%1,%2,%3};"
        : "+f"(c[0]), "+f"(c[1]), "+f"(c[2]), "+f"(c[3])
        : "r"(a[0]), "r"(a[1]), "r"(a[2]), "r"(a[3]), "r"(b[0]), "r"(b[1]));
}
// A row-major [16 x K] in smem, stride in halves (even), k0 multiple of 16
__device__ __forceinline__ void lda(unsigned* a, const __half* base, int stride,
                                    int k0, int lane) {
    int gr = lane >> 2, gc = lane & 3;
    const __half* p = base + gr * stride + k0 + 2 * gc;
    a[0] = *(const unsigned*)p;
    a[1] = *(const unsigned*)(p + 8 * stride);
    a[2] = *(const unsigned*)(p + 8);
    a[3] = *(const unsigned*)(p + 8 * stride + 8);
}
// B as WT[n][k] row-major (= B col-major), stride in halves
__device__ __forceinline__ void ldb(unsigned* b, const __half* WT, int stride,
                                    int n0, int k0, int lane) {
    int gn = lane >> 2, gc = lane & 3;
    const __half* p = WT + (n0 + gn) * stride + k0 + 2 * gc;
    b[0] = *(const unsigned*)p;
    b[1] = *(const unsigned*)(p + 8);
}
// loop1 A-operand element pair straight from gmem.
// logical col ka in [0,96): [0,32)=accP2*ivp, [32,64)=accN2*ivn, [64,96)=xpn.
// off = 0 for the "p" variant (A|B|xp), 32 for the "n" variant (C|D|xn).
__device__ __forceinline__ unsigned ldA96(int n, int ka, int off,
                                          __half2 ivp, __half2 ivn) {
    __half2 v;
    if (ka < 32) {
        v = *(const __half2*)(g_accP2h + (size_t)n * 64 + off + ka);
        v = __hmul2(v, ivp);
    } else if (ka < 64) {
        v = *(const __half2*)(g_accN2h + (size_t)n * 64 + off + (ka - 32));
        v = __hmul2(v, ivn);
    } else {
        v = *(const __half2*)(g_xpnh + (size_t)n * 64 + off + (ka - 64));
    }
    return *(unsigned*)&v;
}

// ---------- fused init (pack edges + counts + zero accs) + projection -------
// blocks [0, n_blks_proj): projection GEMM [N x 64] @ [64 x 128], grid-stride
// over tiles. blocks [n_blks_proj, gridDim.x): edge pack + counts + zeroing.
__global__ void __launch_bounds__(256)
k_initproj(const float* __restrict__ x,
           const float* __restrict__ Wp1, const float* __restrict__ bp1,
           const float* __restrict__ Wn1, const float* __restrict__ bn1,
           const int* __restrict__ ei, int E, int n_nodes, int n_tiles,
           int n_blks_proj) {
    int tid = threadIdx.x;
    if ((int)blockIdx.x >= n_blks_proj) {
        // ---------------- init partition ----------------
        int ib = blockIdx.x - n_blks_proj;
        int nib = gridDim.x - n_blks_proj;
        int i = ib * 256 + tid;
        int stride = nib * 256;
        for (int e = i; e < E; e += stride) {
            long eb = 3L * e;
            int s  = __ldg(ei + eb);
            int d  = __ldg(ei + eb + 1);
            int sg = __ldg(ei + eb + 2);
            bool pos = (sg > 0);
            g_es[e] = make_int2(s, pos ? d : ~d);
            atomicAdd(pos ? (g_cntp + d) : (g_cntn + d), 1.0f);
        }
        uint4 z4 = make_uint4(0u, 0u, 0u, 0u);
        int nh = n_nodes * 4;
        for (int j = i; j < nh; j += stride) {
            ((uint4*)g_accPh)[j] = z4;
            ((uint4*)g_accNh)[j] = z4;
        }
        int nd = n_nodes * 8;
        for (int j = i; j < nd; j += stride) {
            ((uint4*)g_accP2h)[j] = z4;
            ((uint4*)g_accN2h)[j] = z4;
        }
        return;
    }

    // ---------------- projection partition ----------------
    __shared__ __align__(16) __half WT[128 * 72];
    __shared__ float b1s[64];
    for (int i = tid; i < 64 * 128; i += 256) {
        int k = i >> 7, col = i & 127;
        float w;
        if (col < 32)       w = Wp1[k * 32 + col];
        else if (col < 64)  w = Wn1[k * 32 + (col - 32)];
        else if (col < 96)  w = Wp1[(64 + k) * 32 + (col - 64)];
        else                w = Wn1[(64 + k) * 32 + (col - 96)];
        WT[col * 72 + k] = __float2half(w);
    }
    if (tid < 32) { b1s[tid] = bp1[tid]; b1s[32 + tid] = bn1[tid]; }
    __syncthreads();

    int wid = tid >> 5, lane = tid & 31;
    int gr = lane >> 2, gc = lane & 3;
    int tile_stride = n_blks_proj * 8;

    for (int tile = blockIdx.x * 8 + wid; tile < n_tiles; tile += tile_stride) {
        int base = tile * 16;
        int r0 = base + gr, r1 = base + gr + 8;
        bool v0 = r0 < n_nodes, v1 = r1 < n_nodes;
        size_t rr0 = v0 ? (size_t)r0 : 0, rr1 = v1 ? (size_t)r1 : 0;

        float c[16][4];
#pragma unroll
        for (int t = 0; t < 16; t++)
            c[t][0] = c[t][1] = c[t][2] = c[t][3] = 0.f;

        for (int kc = 0; kc < 4; kc++) {
            unsigned a[4];
            const float* p0 = x + rr0 * 64 + 16 * kc + 2 * gc;
            const float* p1 = x + rr1 * 64 + 16 * kc + 2 * gc;
            float2 f0 = *(const float2*)p0;
            float2 f1 = *(const float2*)p1;
            float2 f2 = *(const float2*)(p0 + 8);
            float2 f3 = *(const float2*)(p1 + 8);
            a[0] = packh2(f0.x, f0.y);
            a[1] = packh2(f1.x, f1.y);
            a[2] = packh2(f2.x, f2.y);
            a[3] = packh2(f3.x, f3.y);
#pragma unroll
            for (int t = 0; t < 16; t++) {
                unsigned b[2];
                ldb(b, WT, 72, 8 * t, 16 * kc, lane);
                mma16816(c[t], a, b);
            }
        }
#pragma unroll
        for (int t = 0; t < 16; t++) {
            int colw = 8 * t + 2 * gc;
            if (colw < 64) {
                __half* dstb = (colw < 32) ? g_Ph : g_Qh;
                int cw = colw & 31;
                if (v0) *(unsigned*)(dstb + rr0 * 32 + cw) = packh2(c[t][0], c[t][1]);
                if (v1) *(unsigned*)(dstb + rr1 * 32 + cw) = packh2(c[t][2], c[t][3]);
            } else {
                float bb0 = b1s[colw - 64], bb1 = b1s[colw - 63];
                if (v0) *(unsigned*)(g_RSh + rr0 * 64 + (colw - 64)) =
                    packh2(c[t][0] + bb0, c[t][1] + bb1);
                if (v1) *(unsigned*)(g_RSh + rr1 * 64 + (colw - 64)) =
                    packh2(c[t][2] + bb0, c[t][3] + bb1);
            }
        }
    }
}

// --------------------------- layer-1 aggregation ----------------------------
// 2 edges per thread; 4 chunk-threads per edge pair. (counts done in init)
__global__ void k_edge1(int npairs, int E) {
    long idx = (long)blockIdx.x * blockDim.x + threadIdx.x;
    int p = (int)(idx >> 2);
    if (p >= npairs) return;
    int c = (int)(idx & 3);
    int4 es = __ldg((const int4*)g_es + p);
    bool has1 = (2 * p + 1 < E);

    int s0 = es.x, d0 = es.y;
    bool pos0 = (d0 >= 0);
    if (!pos0) d0 = ~d0;
    int s1 = es.z, d1 = es.w;
    bool pos1 = (d1 >= 0);
    if (!pos1) d1 = ~d1;

    uint4 v0 = *((const uint4*)(pos0 ? g_Ph : g_Qh) + (size_t)s0 * 4 + c);
    uint4 v1;
    if (has1) v1 = *((const uint4*)(pos1 ? g_Ph : g_Qh) + (size_t)s1 * 4 + c);

    red_v4h((pos0 ? g_accPh : g_accNh) + (size_t)d0 * 32 + c * 8, v0);
    if (has1)
        red_v4h((pos1 ? g_accPh : g_accNh) + (size_t)d1 * 32 + c * 8, v1);
}

// --------------------- node layer 1: elementwise tanh -----------------------
__global__ void k_node1e(long total) {
    long idx = (long)blockIdx.x * blockDim.x + threadIdx.x;
    if (idx >= total) return;
    int n = (int)(idx >> 3);
    int c = (int)(idx & 7);
    uint4 rs = ((const uint4*)g_RSh)[idx];
    uint4 acc;
    float inv;
    if (c < 4) {
        acc = ((const uint4*)g_accPh)[(size_t)n * 4 + c];
        inv = 1.0f / fmaxf(g_cntp[n], 1.0f);
    } else {
        acc = ((const uint4*)g_accNh)[(size_t)n * 4 + (c - 4)];
        inv = 1.0f / fmaxf(g_cntn[n], 1.0f);
    }
    float rf[8], af[8];
    h8tof(rs, rf);
    h8tof(acc, af);
    uint4 o;
    unsigned* ou = (unsigned*)&o;
#pragma unroll
    for (int j = 0; j < 4; j++)
        ou[j] = packh2(ftanh(rf[2 * j] + af[2 * j] * inv),
                       ftanh(rf[2 * j + 1] + af[2 * j + 1] * inv));
    ((uint4*)g_xpnh)[idx] = o;
}

// --------------------------- layer-2 aggregation ----------------------------
// 2 edges per thread; 8 chunk-threads per edge pair.
__global__ void k_edge2(int npairs, int E) {
    long idx = (long)blockIdx.x * blockDim.x + threadIdx.x;
    int p = (int)(idx >> 3);
    if (p >= npairs) return;
    int c = (int)(idx & 7);
    int4 es = __ldg((const int4*)g_es + p);
    bool has1 = (2 * p + 1 < E);

    int s0 = es.x, d0 = es.y;
    int s1 = es.z, d1 = es.w;

    uint4 v0 = *((const uint4*)g_xpnh + (size_t)s0 * 8 + c);
    uint4 v1;
    if (has1) v1 = *((const uint4*)g_xpnh + (size_t)s1 * 8 + c);

    if (d0 >= 0) {
        red_v4h(g_accP2h + (size_t)d0 * 64 + c * 8, v0);
    } else {
        red_v4h(g_accN2h + (size_t)(~d0) * 64 + (((c + 4) & 7)) * 8, v0);
    }
    if (has1) {
        if (d1 >= 0) {
            red_v4h(g_accP2h + (size_t)d1 * 64 + c * 8, v1);
        } else {
            red_v4h(g_accN2h + (size_t)(~d1) * 64 + (((c + 4) & 7)) * 8, v1);
        }
    }
}

// ------------- node layer 2 + MLP head: tensor-core warp tiles --------------
// grid-stride over tiles; weights staged once per block. Counts re-zeroed.
__global__ void __launch_bounds__(256, 2)
k_node2TC(const float* __restrict__ Wp2, const float* __restrict__ bp2,
          const float* __restrict__ Wn2, const float* __restrict__ bn2,
          const float* __restrict__ Ww,  const float* __restrict__ bw,
          const float* __restrict__ Wm1, const float* __restrict__ bm1,
          const float* __restrict__ g1,  const float* __restrict__ be1,
          const float* __restrict__ rm1, const float* __restrict__ rv1,
          const float* __restrict__ Wm2, const float* __restrict__ bm2,
          const float* __restrict__ g2,  const float* __restrict__ be2,
          const float* __restrict__ rm2, const float* __restrict__ rv2,
          const float* __restrict__ Wm3, const float* __restrict__ bm3,
          float* __restrict__ outz, float* __restrict__ outp,
          int n_nodes, int n_tiles) {
    extern __shared__ __align__(16) __half smh[];
    __half* WpT = smh;                    // 32 x 104
    __half* WnT = smh + 3328;             // 32 x 104
    __half* WwT = smh + 6656;             // 64 x 72
    __half* W1T = smh + 11264;            // 64 x 72
    __half* W2T = smh + 15872;            // 64 x 72
    // per-warp z-tile: 16 x 72 halves each
    float* fb = (float*)(smh + 29696);
    float* bp2s = fb;         // 32
    float* bn2s = fb + 32;    // 32
    float* bws  = fb + 64;    // 64
    float* sc1  = fb + 128;   // 64
    float* of1  = fb + 192;   // 64
    float* sc2  = fb + 256;   // 64
    float* of2  = fb + 320;   // 64
    float* w3s  = fb + 384;   // 64
    // fb[448] = b3

    int tid = threadIdx.x;
    for (int i = tid; i < 96 * 32; i += 256) {
        int k = i >> 5, nn = i & 31;
        WpT[nn * 104 + k] = __float2half(Wp2[i]);
        WnT[nn * 104 + k] = __float2half(Wn2[i]);
    }
    for (int i = tid; i < 64 * 64; i += 256) {
        int k = i >> 6, nn = i & 63;
        WwT[nn * 72 + k] = __float2half(Ww[i]);
        W1T[nn * 72 + k] = __float2half(Wm1[i]);
        W2T[nn * 72 + k] = __float2half(Wm2[i]);
    }
    if (tid < 32) { bp2s[tid] = bp2[tid]; bn2s[tid] = bn2[tid]; }
    if (tid < 64) {
        bws[tid] = bw[tid];
        float s1 = g1[tid] * rsqrtf(rv1[tid] + 1e-5f);
        sc1[tid] = s1;
        of1[tid] = (bm1[tid] - rm1[tid]) * s1 + be1[tid];
        float s2 = g2[tid] * rsqrtf(rv2[tid] + 1e-5f);
        sc2[tid] = s2;
        of2[tid] = (bm2[tid] - rm2[tid]) * s2 + be2[tid];
        w3s[tid] = Wm3[tid];
    }
    if (tid == 0) fb[448] = bm3[0];
    __syncthreads();

    int wid = tid >> 5, lane = tid & 31;
    __half* zs = smh + 20480 + wid * 1152;  // 16 x 72
    int gr = lane >> 2, gc = lane & 3;
    int tile_stride = gridDim.x * 8;

    for (int tile = blockIdx.x * 8 + wid; tile < n_tiles; tile += tile_stride) {
        int base = tile * 16;
        int nr0 = base + gr, nr1 = base + gr + 8;
        bool v0 = nr0 < n_nodes, v1 = nr1 < n_nodes;
        int n0 = v0 ? nr0 : (n_nodes - 1);
        int n1 = v1 ? nr1 : (n_nodes - 1);

        __half2 ivp0 = __float2half2_rn(1.0f / fmaxf(g_cntp[n0], 1.0f));
        __half2 ivn0 = __float2half2_rn(1.0f / fmaxf(g_cntn[n0], 1.0f));
        __half2 ivp1 = __float2half2_rn(1.0f / fmaxf(g_cntp[n1], 1.0f));
        __half2 ivn1 = __float2half2_rn(1.0f / fmaxf(g_cntn[n1], 1.0f));
        __syncwarp();
        // re-zero counts for next launch (each valid node owned by exactly
        // one tile; padding reads of a just-zeroed count only produce values
        // discarded by the v0/v1 store guards)
        if (lane < 16) {
            int nz = base + lane;
            if (nz < n_nodes) { g_cntp[nz] = 0.f; g_cntn[nz] = 0.f; }
        }

        // ---- loop1: hp (t 0..3 via WpT), hn (t 4..7 via WnT), K=96, A gmem
        float c1[8][4];
#pragma unroll
        for (int t = 0; t < 8; t++)
            c1[t][0] = c1[t][1] = c1[t][2] = c1[t][3] = 0.f;
#pragma unroll
        for (int kc = 0; kc < 6; kc++) {
            int ka = 16 * kc + 2 * gc;
            unsigned a[4], b[2];
            // p-variant: [A | B | xp]
            a[0] = ldA96(n0, ka, 0, ivp0, ivn0);
            a[1] = ldA96(n1, ka, 0, ivp1, ivn1);
            a[2] = ldA96(n0, ka + 8, 0, ivp0, ivn0);
            a[3] = ldA96(n1, ka + 8, 0, ivp1, ivn1);
#pragma unroll
            for (int t = 0; t < 4; t++) {
                ldb(b, WpT, 104, 8 * t, 16 * kc, lane);
                mma16816(c1[t], a, b);
            }
            // n-variant: [C | D | xn]
            a[0] = ldA96(n0, ka, 32, ivp0, ivn0);
            a[1] = ldA96(n1, ka, 32, ivp1, ivn1);
            a[2] = ldA96(n0, ka + 8, 32, ivp0, ivn0);
            a[3] = ldA96(n1, ka + 8, 32, ivp1, ivn1);
#pragma unroll
            for (int t = 0; t < 4; t++) {
                ldb(b, WnT, 104, 8 * t, 16 * kc, lane);
                mma16816(c1[4 + t], a, b);
            }
        }
#pragma unroll
        for (int t = 0; t < 8; t++) {
            int c32 = 8 * (t & 3) + 2 * gc;
            const float* barr = (t < 4) ? bp2s : bn2s;
            float b0 = barr[c32], b1 = barr[c32 + 1];
            int cz = (t < 4) ? c32 : 32 + c32;
            *(unsigned*)(zs + gr * 72 + cz) =
                packh2(ftanh(c1[t][0] + b0), ftanh(c1[t][1] + b1));
            *(unsigned*)(zs + (gr + 8) * 72 + cz) =
                packh2(ftanh(c1[t][2] + b0), ftanh(c1[t][3] + b1));
        }
        __syncwarp();

        // ---- loop2: z = tanh(z2 @ Ww + bw) ----
        float c2[8][4];
#pragma unroll
        for (int t = 0; t < 8; t++)
            c2[t][0] = c2[t][1] = c2[t][2] = c2[t][3] = 0.f;
        for (int kc = 0; kc < 4; kc++) {
            unsigned a[4], b[2];
            lda(a, zs, 72, 16 * kc, lane);
#pragma unroll
            for (int t = 0; t < 8; t++) {
                ldb(b, WwT, 72, 8 * t, 16 * kc, lane);
                mma16816(c2[t], a, b);
            }
        }
        __syncwarp();
#pragma unroll
        for (int t = 0; t < 8; t++) {
            int col = 8 * t + 2 * gc;
            float z0 = ftanh(c2[t][0] + bws[col]);
            float z1 = ftanh(c2[t][1] + bws[col + 1]);
            float z2v = ftanh(c2[t][2] + bws[col]);
            float z3 = ftanh(c2[t][3] + bws[col + 1]);
            if (v0) *(float2*)(outz + (size_t)nr0 * 64 + col) = make_float2(z0, z1);
            if (v1) *(float2*)(outz + (size_t)nr1 * 64 + col) = make_float2(z2v, z3);
            *(unsigned*)(zs + gr * 72 + col) = packh2(z0, z1);
            *(unsigned*)(zs + (gr + 8) * 72 + col) = packh2(z2v, z3);
        }
        __syncwarp();

        // ---- loop3: h = relu(bn1(z @ Wm1)) ----
#pragma unroll
        for (int t = 0; t < 8; t++)
            c2[t][0] = c2[t][1] = c2[t][2] = c2[t][3] = 0.f;
        for (int kc = 0; kc < 4; kc++) {
            unsigned a[4], b[2];
            lda(a, zs, 72, 16 * kc, lane);
#pragma unroll
            for (int t = 0; t < 8; t++) {
                ldb(b, W1T, 72, 8 * t, 16 * kc, lane);
                mma16816(c2[t], a, b);
            }
        }
        __syncwarp();
#pragma unroll
        for (int t = 0; t < 8; t++) {
            int col = 8 * t + 2 * gc;
            float h0 = fmaxf(c2[t][0] * sc1[col] + of1[col], 0.f);
            float h1 = fmaxf(c2[t][1] * sc1[col + 1] + of1[col + 1], 0.f);
            float h2 = fmaxf(c2[t][2] * sc1[col] + of1[col], 0.f);
            float h3 = fmaxf(c2[t][3] * sc1[col + 1] + of1[col + 1], 0.f);
            *(unsigned*)(zs + gr * 72 + col) = packh2(h0, h1);
            *(unsigned*)(zs + (gr + 8) * 72 + col) = packh2(h2, h3);
        }
        __syncwarp();

        // ---- loop4: r = relu(bn2(h @ Wm2)); prob = sigmoid(r.w3 + b3) ----
#pragma unroll
        for (int t = 0; t < 8; t++)
            c2[t][0] = c2[t][1] = c2[t][2] = c2[t][3] = 0.f;
        for (int kc = 0; kc < 4; kc++) {
            unsigned a[4], b[2];
            lda(a, zs, 72, 16 * kc, lane);
#pragma unroll
            for (int t = 0; t < 8; t++) {
                ldb(b, W2T, 72, 8 * t, 16 * kc, lane);
                mma16816(c2[t], a, b);
            }
        }
        float p0 = 0.f, p1 = 0.f;
#pragma unroll
        for (int t = 0; t < 8; t++) {
            int col = 8 * t + 2 * gc;
            float r0 = fmaxf(c2[t][0] * sc2[col] + of2[col], 0.f);
            float r1 = fmaxf(c2[t][1] * sc2[col + 1] + of2[col + 1], 0.f);
            float r2 = fmaxf(c2[t][2] * sc2[col] + of2[col], 0.f);
            float r3 = fmaxf(c2[t][3] * sc2[col + 1] + of2[col + 1], 0.f);
            p0 += r0 * w3s[col] + r1 * w3s[col + 1];
            p1 += r2 * w3s[col] + r3 * w3s[col + 1];
        }
        p0 += __shfl_xor_sync(0xffffffffu, p0, 1);
        p0 += __shfl_xor_sync(0xffffffffu, p0, 2);
        p1 += __shfl_xor_sync(0xffffffffu, p1, 1);
        p1 += __shfl_xor_sync(0xffffffffu, p1, 2);
        if ((lane & 3) == 0) {
            float b3 = fb[448];
            if (v0) outp[nr0] = __fdividef(1.0f, 1.0f + __expf(-(p0 + b3)));
            if (v1) outp[nr1] = __fdividef(1.0f, 1.0f + __expf(-(p1 + b3)));
        }
        __syncwarp();
    }
}

// -------------------------------- launcher ----------------------------------
extern "C" void kernel_launch(void* const* d_in, const int* in_sizes, int n_in,
                              void* d_out, int out_size) {
    const float* x   = (const float*)d_in[0];
    const int*   ei  = (const int*)d_in[1];
    const float* Wp1 = (const float*)d_in[2];
    const float* bp1 = (const float*)d_in[3];
    const float* Wn1 = (const float*)d_in[4];
    const float* bn1 = (const float*)d_in[5];
    const float* Wp2 = (const float*)d_in[6];
    const float* bp2 = (const float*)d_in[7];
    const float* Wn2 = (const float*)d_in[8];
    const float* bn2 = (const float*)d_in[9];
    const float* Ww  = (const float*)d_in[10];
    const float* bw  = (const float*)d_in[11];
    const float* Wm1 = (const float*)d_in[12];
    const float* bm1 = (const float*)d_in[13];
    const float* g1  = (const float*)d_in[14];
    const float* be1 = (const float*)d_in[15];
    const float* rm1 = (const float*)d_in[16];
    const float* rv1 = (const float*)d_in[17];
    const float* Wm2 = (const float*)d_in[18];
    const float* bm2 = (const float*)d_in[19];
    const float* g2  = (const float*)d_in[20];
    const float* be2 = (const float*)d_in[21];
    const float* rm2 = (const float*)d_in[22];
    const float* rv2 = (const float*)d_in[23];
    const float* Wm3 = (const float*)d_in[24];
    const float* bm3 = (const float*)d_in[25];

    int Nn = in_sizes[0] / DD;
    int E  = in_sizes[1] / 3;

    float* out  = (float*)d_out;
    float* outz = out;
    float* outp = out + (size_t)Nn * DD;

    int n_tiles = (Nn + 15) / 16;
    int max_blks = (n_tiles + 7) / 8;
    int n_blks_proj = max_blks < 296 ? max_blks : 296;
    int n_blks_init = 296;
    int n_blks2 = max_blks < 296 ? max_blks : 296;
    int npairs  = (E + 1) / 2;

    const int NODE2_SMEM = 29696 * 2 + 452 * 4;  // 61200 B
    cudaFuncSetAttribute(k_node2TC, cudaFuncAttributeMaxDynamicSharedMemorySize,
                         NODE2_SMEM);

    k_initproj<<<n_blks_proj + n_blks_init, 256>>>(
        x, Wp1, bp1, Wn1, bn1, ei, E, Nn, n_tiles, n_blks_proj);

    long t1 = (long)npairs * 4;
    k_edge1<<<(int)((t1 + 255) / 256), 256>>>(npairs, E);

    long tn = (long)Nn * 8;
    k_node1e<<<(int)((tn + 255) / 256), 256>>>(tn);

    long t2 = (long)npairs * 8;
    k_edge2<<<(int)((t2 + 255) / 256), 256>>>(npairs, E);

    k_node2TC<<<n_blks2, 256, NODE2_SMEM>>>(
        Wp2, bp2, Wn2, bn2, Ww, bw,
        Wm1, bm1, g1, be1, rm1, rv1,
        Wm2, bm2, g2, be2, rm2, rv2,
        Wm3, bm3, outz, outp, Nn, n_tiles);
}

// round 13
// speedup vs baseline: 1.5969x; 1.0128x over previous
#include <cuda_runtime.h>
#include <cuda_fp16.h>
#include <math.h>

#define NMAX 100000
#define EMAX 1310720
#define DD 64

// -------- persistent scratch (device globals; no allocation allowed) --------
__device__ __align__(16) __half g_Ph[NMAX * 32];     // x @ Wp1[:64]
__device__ __align__(16) __half g_Qh[NMAX * 32];     // x @ Wn1[:64]
__device__ __align__(16) __half g_RSh[NMAX * 64];    // [x@Wp1[64:]+bp1 | x@Wn1[64:]+bn1]
__device__ __align__(16) __half g_accPh[NMAX * 32];
__device__ __align__(16) __half g_accNh[NMAX * 32];
__device__ __align__(16) __half g_xpnh[NMAX * 64];   // [xp | xn]
__device__ __align__(16) __half g_accP2h[NMAX * 64]; // pos: [sum xp | sum xn] = [A|C]
__device__ __align__(16) __half g_accN2h[NMAX * 64]; // neg: [sum xn | sum xp] = [B|D]
__device__ __align__(16) float  g_cntp[NMAX];        // zeroed at END of node2TC
__device__ __align__(16) float  g_cntn[NMAX];
__device__ __align__(16) int2   g_es[EMAX];          // {src, dst or ~dst(neg)}

// ------------------------------ tiny helpers --------------------------------
__device__ __forceinline__ void red_v4h(__half* p, uint4 v) {
    asm volatile("red.global.add.noftz.v4.f16x2 [%0], {%1,%2,%3,%4};"
                 :: "l"(p), "r"(v.x), "r"(v.y), "r"(v.z), "r"(v.w)
                 : "memory");
}
__device__ __forceinline__ unsigned packh2(float a, float b) {
    __half2 h = __floats2half2_rn(a, b);
    return *(unsigned*)&h;
}
__device__ __forceinline__ void h8tof(uint4 v, float* o) {
    const __half2* h = (const __half2*)&v;
#pragma unroll
    for (int j = 0; j < 4; j++) {
        float2 f = __half22float2(h[j]);
        o[2 * j] = f.x;
        o[2 * j + 1] = f.y;
    }
}
// fast tanh: 1 - 2/(exp(2x)+1); inf-safe at both ends, rel err ~1e-6
__device__ __forceinline__ float ftanh(float x) {
    float e = __expf(2.0f * x);
    return 1.0f - __fdividef(2.0f, e + 1.0f);
}

// ---------------- mma.m16n8k16 f16 -> f32, analytic fragments ---------------
__device__ __forceinline__ void mma16816(float* c, const unsigned* a, const unsigned* b) {
    asm volatile(
        "mma.sync.aligned.m16n8k16.row.col.f32.f16.f16.f32 "
        "{%0,%1,%2,%3}, {%4,%5,%6,%7}, {%8,%9}, {%0,%1,%2,%3};"
        : "+f"(c[0]), "+f"(c[1]), "+f"(c[2]), "+f"(c[3])
        : "r"(a[0]), "r"(a[1]), "r"(a[2]), "r"(a[3]), "r"(b[0]), "r"(b[1]));
}
// A row-major [16 x K] in smem, stride in halves (even), k0 multiple of 16
__device__ __forceinline__ void lda(unsigned* a, const __half* base, int stride,
                                    int k0, int lane) {
    int gr = lane >> 2, gc = lane & 3;
    const __half* p = base + gr * stride + k0 + 2 * gc;
    a[0] = *(const unsigned*)p;
    a[1] = *(const unsigned*)(p + 8 * stride);
    a[2] = *(const unsigned*)(p + 8);
    a[3] = *(const unsigned*)(p + 8 * stride + 8);
}
// B as WT[n][k] row-major (= B col-major), stride in halves
__device__ __forceinline__ void ldb(unsigned* b, const __half* WT, int stride,
                                    int n0, int k0, int lane) {
    int gn = lane >> 2, gc = lane & 3;
    const __half* p = WT + (n0 + gn) * stride + k0 + 2 * gc;
    b[0] = *(const unsigned*)p;
    b[1] = *(const unsigned*)(p + 8);
}
// loop1 A-operand element pair straight from gmem.
// logical col ka in [0,96): [0,32)=accP2*ivp, [32,64)=accN2*ivn, [64,96)=xpn.
// off = 0 for the "p" variant (A|B|xp), 32 for the "n" variant (C|D|xn).
__device__ __forceinline__ unsigned ldA96(int n, int ka, int off,
                                          __half2 ivp, __half2 ivn) {
    __half2 v;
    if (ka < 32) {
        v = *(const __half2*)(g_accP2h + (size_t)n * 64 + off + ka);
        v = __hmul2(v, ivp);
    } else if (ka < 64) {
        v = *(const __half2*)(g_accN2h + (size_t)n * 64 + off + (ka - 32));
        v = __hmul2(v, ivn);
    } else {
        v = *(const __half2*)(g_xpnh + (size_t)n * 64 + off + (ka - 64));
    }
    return *(unsigned*)&v;
}

// ---------- fused init (pack edges + counts + zero accs) + projection -------
// blocks [0, n_blks_proj): projection GEMM [N x 64] @ [64 x 128], grid-stride
// over tiles. blocks [n_blks_proj, gridDim.x): edge pack + counts + zeroing.
__global__ void __launch_bounds__(256)
k_initproj(const float* __restrict__ x,
           const float* __restrict__ Wp1, const float* __restrict__ bp1,
           const float* __restrict__ Wn1, const float* __restrict__ bn1,
           const int* __restrict__ ei, int E, int n_nodes, int n_tiles,
           int n_blks_proj) {
    int tid = threadIdx.x;
    if ((int)blockIdx.x >= n_blks_proj) {
        // ---------------- init partition ----------------
        int ib = blockIdx.x - n_blks_proj;
        int nib = gridDim.x - n_blks_proj;
        int i = ib * 256 + tid;
        int stride = nib * 256;
        for (int e = i; e < E; e += stride) {
            long eb = 3L * e;
            int s  = __ldg(ei + eb);
            int d  = __ldg(ei + eb + 1);
            int sg = __ldg(ei + eb + 2);
            bool pos = (sg > 0);
            g_es[e] = make_int2(s, pos ? d : ~d);
            atomicAdd(pos ? (g_cntp + d) : (g_cntn + d), 1.0f);
        }
        uint4 z4 = make_uint4(0u, 0u, 0u, 0u);
        int nh = n_nodes * 4;
        for (int j = i; j < nh; j += stride) {
            ((uint4*)g_accPh)[j] = z4;
            ((uint4*)g_accNh)[j] = z4;
        }
        int nd = n_nodes * 8;
        for (int j = i; j < nd; j += stride) {
            ((uint4*)g_accP2h)[j] = z4;
            ((uint4*)g_accN2h)[j] = z4;
        }
        return;
    }

    // ---------------- projection partition ----------------
    __shared__ __align__(16) __half WT[128 * 72];
    __shared__ float b1s[64];
    for (int i = tid; i < 64 * 128; i += 256) {
        int k = i >> 7, col = i & 127;
        float w;
        if (col < 32)       w = Wp1[k * 32 + col];
        else if (col < 64)  w = Wn1[k * 32 + (col - 32)];
        else if (col < 96)  w = Wp1[(64 + k) * 32 + (col - 64)];
        else                w = Wn1[(64 + k) * 32 + (col - 96)];
        WT[col * 72 + k] = __float2half(w);
    }
    if (tid < 32) { b1s[tid] = bp1[tid]; b1s[32 + tid] = bn1[tid]; }
    __syncthreads();

    int wid = tid >> 5, lane = tid & 31;
    int gr = lane >> 2, gc = lane & 3;
    int tile_stride = n_blks_proj * 8;

    for (int tile = blockIdx.x * 8 + wid; tile < n_tiles; tile += tile_stride) {
        int base = tile * 16;
        int r0 = base + gr, r1 = base + gr + 8;
        bool v0 = r0 < n_nodes, v1 = r1 < n_nodes;
        size_t rr0 = v0 ? (size_t)r0 : 0, rr1 = v1 ? (size_t)r1 : 0;

        // prefetch ALL A fragments (16 regs) before any mma
        unsigned af[16];
#pragma unroll
        for (int kc = 0; kc < 4; kc++) {
            const float* p0 = x + rr0 * 64 + 16 * kc + 2 * gc;
            const float* p1 = x + rr1 * 64 + 16 * kc + 2 * gc;
            float2 f0 = *(const float2*)p0;
            float2 f1 = *(const float2*)p1;
            float2 f2 = *(const float2*)(p0 + 8);
            float2 f3 = *(const float2*)(p1 + 8);
            af[4 * kc]     = packh2(f0.x, f0.y);
            af[4 * kc + 1] = packh2(f1.x, f1.y);
            af[4 * kc + 2] = packh2(f2.x, f2.y);
            af[4 * kc + 3] = packh2(f3.x, f3.y);
        }

        float c[16][4];
#pragma unroll
        for (int t = 0; t < 16; t++)
            c[t][0] = c[t][1] = c[t][2] = c[t][3] = 0.f;

#pragma unroll
        for (int kc = 0; kc < 4; kc++) {
#pragma unroll
            for (int t = 0; t < 16; t++) {
                unsigned b[2];
                ldb(b, WT, 72, 8 * t, 16 * kc, lane);
                mma16816(c[t], af + 4 * kc, b);
            }
        }
#pragma unroll
        for (int t = 0; t < 16; t++) {
            int colw = 8 * t + 2 * gc;
            if (colw < 64) {
                __half* dstb = (colw < 32) ? g_Ph : g_Qh;
                int cw = colw & 31;
                if (v0) *(unsigned*)(dstb + rr0 * 32 + cw) = packh2(c[t][0], c[t][1]);
                if (v1) *(unsigned*)(dstb + rr1 * 32 + cw) = packh2(c[t][2], c[t][3]);
            } else {
                float bb0 = b1s[colw - 64], bb1 = b1s[colw - 63];
                if (v0) *(unsigned*)(g_RSh + rr0 * 64 + (colw - 64)) =
                    packh2(c[t][0] + bb0, c[t][1] + bb1);
                if (v1) *(unsigned*)(g_RSh + rr1 * 64 + (colw - 64)) =
                    packh2(c[t][2] + bb0, c[t][3] + bb1);
            }
        }
    }
}

// --------------------------- layer-1 aggregation ----------------------------
// 2 edges per thread; 4 chunk-threads per edge pair. (counts done in init)
__global__ void k_edge1(int npairs, int E) {
    long idx = (long)blockIdx.x * blockDim.x + threadIdx.x;
    int p = (int)(idx >> 2);
    if (p >= npairs) return;
    int c = (int)(idx & 3);
    int4 es = __ldg((const int4*)g_es + p);
    bool has1 = (2 * p + 1 < E);

    int s0 = es.x, d0 = es.y;
    bool pos0 = (d0 >= 0);
    if (!pos0) d0 = ~d0;
    int s1 = es.z, d1 = es.w;
    bool pos1 = (d1 >= 0);
    if (!pos1) d1 = ~d1;

    uint4 v0 = *((const uint4*)(pos0 ? g_Ph : g_Qh) + (size_t)s0 * 4 + c);
    uint4 v1;
    if (has1) v1 = *((const uint4*)(pos1 ? g_Ph : g_Qh) + (size_t)s1 * 4 + c);

    red_v4h((pos0 ? g_accPh : g_accNh) + (size_t)d0 * 32 + c * 8, v0);
    if (has1)
        red_v4h((pos1 ? g_accPh : g_accNh) + (size_t)d1 * 32 + c * 8, v1);
}

// --------------------- node layer 1: elementwise tanh -----------------------
__global__ void k_node1e(long total) {
    long idx = (long)blockIdx.x * blockDim.x + threadIdx.x;
    if (idx >= total) return;
    int n = (int)(idx >> 3);
    int c = (int)(idx & 7);
    uint4 rs = ((const uint4*)g_RSh)[idx];
    uint4 acc;
    float inv;
    if (c < 4) {
        acc = ((const uint4*)g_accPh)[(size_t)n * 4 + c];
        inv = 1.0f / fmaxf(g_cntp[n], 1.0f);
    } else {
        acc = ((const uint4*)g_accNh)[(size_t)n * 4 + (c - 4)];
        inv = 1.0f / fmaxf(g_cntn[n], 1.0f);
    }
    float rf[8], af[8];
    h8tof(rs, rf);
    h8tof(acc, af);
    uint4 o;
    unsigned* ou = (unsigned*)&o;
#pragma unroll
    for (int j = 0; j < 4; j++)
        ou[j] = packh2(ftanh(rf[2 * j] + af[2 * j] * inv),
                       ftanh(rf[2 * j + 1] + af[2 * j + 1] * inv));
    ((uint4*)g_xpnh)[idx] = o;
}

// --------------------------- layer-2 aggregation ----------------------------
// 2 edges per thread; 8 chunk-threads per edge pair.
__global__ void k_edge2(int npairs, int E) {
    long idx = (long)blockIdx.x * blockDim.x + threadIdx.x;
    int p = (int)(idx >> 3);
    if (p >= npairs) return;
    int c = (int)(idx & 7);
    int4 es = __ldg((const int4*)g_es + p);
    bool has1 = (2 * p + 1 < E);

    int s0 = es.x, d0 = es.y;
    int s1 = es.z, d1 = es.w;

    uint4 v0 = *((const uint4*)g_xpnh + (size_t)s0 * 8 + c);
    uint4 v1;
    if (has1) v1 = *((const uint4*)g_xpnh + (size_t)s1 * 8 + c);

    if (d0 >= 0) {
        red_v4h(g_accP2h + (size_t)d0 * 64 + c * 8, v0);
    } else {
        red_v4h(g_accN2h + (size_t)(~d0) * 64 + (((c + 4) & 7)) * 8, v0);
    }
    if (has1) {
        if (d1 >= 0) {
            red_v4h(g_accP2h + (size_t)d1 * 64 + c * 8, v1);
        } else {
            red_v4h(g_accN2h + (size_t)(~d1) * 64 + (((c + 4) & 7)) * 8, v1);
        }
    }
}

// ------------- node layer 2 + MLP head: tensor-core warp tiles --------------
// grid-stride over tiles; loop1 A-operands fully register-prefetched from gmem.
__global__ void __launch_bounds__(256, 2)
k_node2TC(const float* __restrict__ Wp2, const float* __restrict__ bp2,
          const float* __restrict__ Wn2, const float* __restrict__ bn2,
          const float* __restrict__ Ww,  const float* __restrict__ bw,
          const float* __restrict__ Wm1, const float* __restrict__ bm1,
          const float* __restrict__ g1,  const float* __restrict__ be1,
          const float* __restrict__ rm1, const float* __restrict__ rv1,
          const float* __restrict__ Wm2, const float* __restrict__ bm2,
          const float* __restrict__ g2,  const float* __restrict__ be2,
          const float* __restrict__ rm2, const float* __restrict__ rv2,
          const float* __restrict__ Wm3, const float* __restrict__ bm3,
          float* __restrict__ outz, float* __restrict__ outp,
          int n_nodes, int n_tiles) {
    extern __shared__ __align__(16) __half smh[];
    __half* WpT = smh;                    // 32 x 104
    __half* WnT = smh + 3328;             // 32 x 104
    __half* WwT = smh + 6656;             // 64 x 72
    __half* W1T = smh + 11264;            // 64 x 72
    __half* W2T = smh + 15872;            // 64 x 72
    // per-warp z-tile: 16 x 72 halves each
    float* fb = (float*)(smh + 29696);
    float* bp2s = fb;         // 32
    float* bn2s = fb + 32;    // 32
    float* bws  = fb + 64;    // 64
    float* sc1  = fb + 128;   // 64
    float* of1  = fb + 192;   // 64
    float* sc2  = fb + 256;   // 64
    float* of2  = fb + 320;   // 64
    float* w3s  = fb + 384;   // 64
    // fb[448] = b3

    int tid = threadIdx.x;
    for (int i = tid; i < 96 * 32; i += 256) {
        int k = i >> 5, nn = i & 31;
        WpT[nn * 104 + k] = __float2half(Wp2[i]);
        WnT[nn * 104 + k] = __float2half(Wn2[i]);
    }
    for (int i = tid; i < 64 * 64; i += 256) {
        int k = i >> 6, nn = i & 63;
        WwT[nn * 72 + k] = __float2half(Ww[i]);
        W1T[nn * 72 + k] = __float2half(Wm1[i]);
        W2T[nn * 72 + k] = __float2half(Wm2[i]);
    }
    if (tid < 32) { bp2s[tid] = bp2[tid]; bn2s[tid] = bn2[tid]; }
    if (tid < 64) {
        bws[tid] = bw[tid];
        float s1 = g1[tid] * rsqrtf(rv1[tid] + 1e-5f);
        sc1[tid] = s1;
        of1[tid] = (bm1[tid] - rm1[tid]) * s1 + be1[tid];
        float s2 = g2[tid] * rsqrtf(rv2[tid] + 1e-5f);
        sc2[tid] = s2;
        of2[tid] = (bm2[tid] - rm2[tid]) * s2 + be2[tid];
        w3s[tid] = Wm3[tid];
    }
    if (tid == 0) fb[448] = bm3[0];
    __syncthreads();

    int wid = tid >> 5, lane = tid & 31;
    __half* zs = smh + 20480 + wid * 1152;  // 16 x 72
    int gr = lane >> 2, gc = lane & 3;
    int tile_stride = gridDim.x * 8;

    for (int tile = blockIdx.x * 8 + wid; tile < n_tiles; tile += tile_stride) {
        int base = tile * 16;
        int nr0 = base + gr, nr1 = base + gr + 8;
        bool v0 = nr0 < n_nodes, v1 = nr1 < n_nodes;
        int n0 = v0 ? nr0 : (n_nodes - 1);
        int n1 = v1 ? nr1 : (n_nodes - 1);

        __half2 ivp0 = __float2half2_rn(1.0f / fmaxf(g_cntp[n0], 1.0f));
        __half2 ivn0 = __float2half2_rn(1.0f / fmaxf(g_cntn[n0], 1.0f));
        __half2 ivp1 = __float2half2_rn(1.0f / fmaxf(g_cntp[n1], 1.0f));
        __half2 ivn1 = __float2half2_rn(1.0f / fmaxf(g_cntn[n1], 1.0f));
        __syncwarp();
        // re-zero counts for next launch (each valid node owned by exactly
        // one tile; padding reads of a just-zeroed count only produce values
        // discarded by the v0/v1 store guards)
        if (lane < 16) {
            int nz = base + lane;
            if (nz < n_nodes) { g_cntp[nz] = 0.f; g_cntn[nz] = 0.f; }
        }

        // ---- loop1 prefetch: ALL 48 A-fragment words issued before any mma
        unsigned ap[24], an[24];
#pragma unroll
        for (int kc = 0; kc < 6; kc++) {
            int ka = 16 * kc + 2 * gc;
            ap[4 * kc]     = ldA96(n0, ka, 0, ivp0, ivn0);
            ap[4 * kc + 1] = ldA96(n1, ka, 0, ivp1, ivn1);
            ap[4 * kc + 2] = ldA96(n0, ka + 8, 0, ivp0, ivn0);
            ap[4 * kc + 3] = ldA96(n1, ka + 8, 0, ivp1, ivn1);
            an[4 * kc]     = ldA96(n0, ka, 32, ivp0, ivn0);
            an[4 * kc + 1] = ldA96(n1, ka, 32, ivp1, ivn1);
            an[4 * kc + 2] = ldA96(n0, ka + 8, 32, ivp0, ivn0);
            an[4 * kc + 3] = ldA96(n1, ka + 8, 32, ivp1, ivn1);
        }

        // ---- loop1 mma: hp (t 0..3 via WpT), hn (t 4..7 via WnT), K = 96
        float c1[8][4];
#pragma unroll
        for (int t = 0; t < 8; t++)
            c1[t][0] = c1[t][1] = c1[t][2] = c1[t][3] = 0.f;
#pragma unroll
        for (int kc = 0; kc < 6; kc++) {
            unsigned b[2];
#pragma unroll
            for (int t = 0; t < 4; t++) {
                ldb(b, WpT, 104, 8 * t, 16 * kc, lane);
                mma16816(c1[t], ap + 4 * kc, b);
            }
#pragma unroll
            for (int t = 0; t < 4; t++) {
                ldb(b, WnT, 104, 8 * t, 16 * kc, lane);
                mma16816(c1[4 + t], an + 4 * kc, b);
            }
        }
#pragma unroll
        for (int t = 0; t < 8; t++) {
            int c32 = 8 * (t & 3) + 2 * gc;
            const float* barr = (t < 4) ? bp2s : bn2s;
            float b0 = barr[c32], b1 = barr[c32 + 1];
            int cz = (t < 4) ? c32 : 32 + c32;
            *(unsigned*)(zs + gr * 72 + cz) =
                packh2(ftanh(c1[t][0] + b0), ftanh(c1[t][1] + b1));
            *(unsigned*)(zs + (gr + 8) * 72 + cz) =
                packh2(ftanh(c1[t][2] + b0), ftanh(c1[t][3] + b1));
        }
        __syncwarp();

        // ---- loop2: z = tanh(z2 @ Ww + bw) ----
        float c2[8][4];
#pragma unroll
        for (int t = 0; t < 8; t++)
            c2[t][0] = c2[t][1] = c2[t][2] = c2[t][3] = 0.f;
        for (int kc = 0; kc < 4; kc++) {
            unsigned a[4], b[2];
            lda(a, zs, 72, 16 * kc, lane);
#pragma unroll
            for (int t = 0; t < 8; t++) {
                ldb(b, WwT, 72, 8 * t, 16 * kc, lane);
                mma16816(c2[t], a, b);
            }
        }
        __syncwarp();
#pragma unroll
        for (int t = 0; t < 8; t++) {
            int col = 8 * t + 2 * gc;
            float z0 = ftanh(c2[t][0] + bws[col]);
            float z1 = ftanh(c2[t][1] + bws[col + 1]);
            float z2v = ftanh(c2[t][2] + bws[col]);
            float z3 = ftanh(c2[t][3] + bws[col + 1]);
            if (v0) *(float2*)(outz + (size_t)nr0 * 64 + col) = make_float2(z0, z1);
            if (v1) *(float2*)(outz + (size_t)nr1 * 64 + col) = make_float2(z2v, z3);
            *(unsigned*)(zs + gr * 72 + col) = packh2(z0, z1);
            *(unsigned*)(zs + (gr + 8) * 72 + col) = packh2(z2v, z3);
        }
        __syncwarp();

        // ---- loop3: h = relu(bn1(z @ Wm1)) ----
#pragma unroll
        for (int t = 0; t < 8; t++)
            c2[t][0] = c2[t][1] = c2[t][2] = c2[t][3] = 0.f;
        for (int kc = 0; kc < 4; kc++) {
            unsigned a[4], b[2];
            lda(a, zs, 72, 16 * kc, lane);
#pragma unroll
            for (int t = 0; t < 8; t++) {
                ldb(b, W1T, 72, 8 * t, 16 * kc, lane);
                mma16816(c2[t], a, b);
            }
        }
        __syncwarp();
#pragma unroll
        for (int t = 0; t < 8; t++) {
            int col = 8 * t + 2 * gc;
            float h0 = fmaxf(c2[t][0] * sc1[col] + of1[col], 0.f);
            float h1 = fmaxf(c2[t][1] * sc1[col + 1] + of1[col + 1], 0.f);
            float h2 = fmaxf(c2[t][2] * sc1[col] + of1[col], 0.f);
            float h3 = fmaxf(c2[t][3] * sc1[col + 1] + of1[col + 1], 0.f);
            *(unsigned*)(zs + gr * 72 + col) = packh2(h0, h1);
            *(unsigned*)(zs + (gr + 8) * 72 + col) = packh2(h2, h3);
        }
        __syncwarp();

        // ---- loop4: r = relu(bn2(h @ Wm2)); prob = sigmoid(r.w3 + b3) ----
#pragma unroll
        for (int t = 0; t < 8; t++)
            c2[t][0] = c2[t][1] = c2[t][2] = c2[t][3] = 0.f;
        for (int kc = 0; kc < 4; kc++) {
            unsigned a[4], b[2];
            lda(a, zs, 72, 16 * kc, lane);
#pragma unroll
            for (int t = 0; t < 8; t++) {
                ldb(b, W2T, 72, 8 * t, 16 * kc, lane);
                mma16816(c2[t], a, b);
            }
        }
        float p0 = 0.f, p1 = 0.f;
#pragma unroll
        for (int t = 0; t < 8; t++) {
            int col = 8 * t + 2 * gc;
            float r0 = fmaxf(c2[t][0] * sc2[col] + of2[col], 0.f);
            float r1 = fmaxf(c2[t][1] * sc2[col + 1] + of2[col + 1], 0.f);
            float r2 = fmaxf(c2[t][2] * sc2[col] + of2[col], 0.f);
            float r3 = fmaxf(c2[t][3] * sc2[col + 1] + of2[col + 1], 0.f);
            p0 += r0 * w3s[col] + r1 * w3s[col + 1];
            p1 += r2 * w3s[col] + r3 * w3s[col + 1];
        }
        p0 += __shfl_xor_sync(0xffffffffu, p0, 1);
        p0 += __shfl_xor_sync(0xffffffffu, p0, 2);
        p1 += __shfl_xor_sync(0xffffffffu, p1, 1);
        p1 += __shfl_xor_sync(0xffffffffu, p1, 2);
        if ((lane & 3) == 0) {
            float b3 = fb[448];
            if (v0) outp[nr0] = __fdividef(1.0f, 1.0f + __expf(-(p0 + b3)));
            if (v1) outp[nr1] = __fdividef(1.0f, 1.0f + __expf(-(p1 + b3)));
        }
        __syncwarp();
    }
}

// -------------------------------- launcher ----------------------------------
extern "C" void kernel_launch(void* const* d_in, const int* in_sizes, int n_in,
                              void* d_out, int out_size) {
    const float* x   = (const float*)d_in[0];
    const int*   ei  = (const int*)d_in[1];
    const float* Wp1 = (const float*)d_in[2];
    const float* bp1 = (const float*)d_in[3];
    const float* Wn1 = (const float*)d_in[4];
    const float* bn1 = (const float*)d_in[5];
    const float* Wp2 = (const float*)d_in[6];
    const float* bp2 = (const float*)d_in[7];
    const float* Wn2 = (const float*)d_in[8];
    const float* bn2 = (const float*)d_in[9];
    const float* Ww  = (const float*)d_in[10];
    const float* bw  = (const float*)d_in[11];
    const float* Wm1 = (const float*)d_in[12];
    const float* bm1 = (const float*)d_in[13];
    const float* g1  = (const float*)d_in[14];
    const float* be1 = (const float*)d_in[15];
    const float* rm1 = (const float*)d_in[16];
    const float* rv1 = (const float*)d_in[17];
    const float* Wm2 = (const float*)d_in[18];
    const float* bm2 = (const float*)d_in[19];
    const float* g2  = (const float*)d_in[20];
    const float* be2 = (const float*)d_in[21];
    const float* rm2 = (const float*)d_in[22];
    const float* rv2 = (const float*)d_in[23];
    const float* Wm3 = (const float*)d_in[24];
    const float* bm3 = (const float*)d_in[25];

    int Nn = in_sizes[0] / DD;
    int E  = in_sizes[1] / 3;

    float* out  = (float*)d_out;
    float* outz = out;
    float* outp = out + (size_t)Nn * DD;

    int n_tiles = (Nn + 15) / 16;
    int max_blks = (n_tiles + 7) / 8;
    int n_blks_proj = max_blks < 296 ? max_blks : 296;
    int n_blks_init = 296;
    int n_blks2 = max_blks < 296 ? max_blks : 296;
    int npairs  = (E + 1) / 2;

    const int NODE2_SMEM = 29696 * 2 + 452 * 4;  // 61200 B
    cudaFuncSetAttribute(k_node2TC, cudaFuncAttributeMaxDynamicSharedMemorySize,
                         NODE2_SMEM);

    k_initproj<<<n_blks_proj + n_blks_init, 256>>>(
        x, Wp1, bp1, Wn1, bn1, ei, E, Nn, n_tiles, n_blks_proj);

    long t1 = (long)npairs * 4;
    k_edge1<<<(int)((t1 + 255) / 256), 256>>>(npairs, E);

    long tn = (long)Nn * 8;
    k_node1e<<<(int)((tn + 255) / 256), 256>>>(tn);

    long t2 = (long)npairs * 8;
    k_edge2<<<(int)((t2 + 255) / 256), 256>>>(npairs, E);

    k_node2TC<<<n_blks2, 256, NODE2_SMEM>>>(
        Wp2, bp2, Wn2, bn2, Ww, bw,
        Wm1, bm1, g1, be1, rm1, rv1,
        Wm2, bm2, g2, be2, rm2, rv2,
        Wm3, bm3, outz, outp, Nn, n_tiles);
}